// round 1
// baseline (speedup 1.0000x reference)
#include <cuda_runtime.h>
#include <math.h>

#define BSZ   16
#define TT    16
#define QQ    100
#define HIDD  256
#define PROJD 256
#define NI    1600    // BS*Q
#define MROWS 25600   // BS*T*Q
#define NNEG  3200

// -------- scratch (device globals; no allocation allowed) --------
__device__ float g_proj[MROWS * PROJD];          // 26.2 MB
__device__ float g_neg[NNEG * TT * PROJD];       // 52.4 MB  [j, t, c]
__device__ float g_nsq[NNEG * TT];               // sum(neg^2) per (j,t)
__device__ float g_a[NI * PROJD];
__device__ float g_asq[NI];
__device__ float g_numer[NI];
__device__ float g_inv2s[NI];
__device__ int   g_bp[NI];
__device__ float g_dist[NI * NNEG];              // 20.5 MB
__device__ float g_self[NI];
__device__ int   g_bucket_start[TT + 1];
__device__ int   g_order[NI];
__device__ float g_brown[NI];
__device__ float g_ht[NI];

__device__ __forceinline__ float warp_sum(float v) {
    #pragma unroll
    for (int o = 16; o > 0; o >>= 1) v += __shfl_xor_sync(0xffffffffu, v, o);
    return v;
}

// ==================== Kernel 1: projection GEMM + bias ====================
// C[m,n] = sum_k A[m,k]*W[k,n] + b[n];  M=25600, N=K=256
#define GBM 64
#define GBN 64
#define GBK 16
__global__ void __launch_bounds__(256) gemm_bias_kernel(
    const float* __restrict__ A, const float* __restrict__ W,
    const float* __restrict__ bias)
{
    __shared__ float As[GBK][GBM];
    __shared__ float Bs[GBK][GBN];
    int tid = threadIdx.x;
    int m0 = blockIdx.y * GBM;
    int n0 = blockIdx.x * GBN;
    int tx = tid & 15;   // n dir (x4)
    int ty = tid >> 4;   // m dir (x4)

    int a_row = tid >> 2;            // 0..63
    int a_col = (tid & 3) * 4;       // 0,4,8,12
    int b_row = tid >> 4;            // 0..15
    int b_col = (tid & 15) * 4;      // 0..60

    float acc[4][4] = {};
    for (int k0 = 0; k0 < HIDD; k0 += GBK) {
        float4 av = *(const float4*)&A[(size_t)(m0 + a_row) * HIDD + k0 + a_col];
        float4 bv = *(const float4*)&W[(size_t)(k0 + b_row) * PROJD + n0 + b_col];
        As[a_col + 0][a_row] = av.x;
        As[a_col + 1][a_row] = av.y;
        As[a_col + 2][a_row] = av.z;
        As[a_col + 3][a_row] = av.w;
        *(float4*)&Bs[b_row][b_col] = bv;
        __syncthreads();
        #pragma unroll
        for (int kk = 0; kk < GBK; kk++) {
            float ar[4], br[4];
            float4 a4 = *(const float4*)&As[kk][ty * 4];
            float4 b4 = *(const float4*)&Bs[kk][tx * 4];
            ar[0]=a4.x; ar[1]=a4.y; ar[2]=a4.z; ar[3]=a4.w;
            br[0]=b4.x; br[1]=b4.y; br[2]=b4.z; br[3]=b4.w;
            #pragma unroll
            for (int i = 0; i < 4; i++)
                #pragma unroll
                for (int j = 0; j < 4; j++)
                    acc[i][j] = fmaf(ar[i], br[j], acc[i][j]);
        }
        __syncthreads();
    }
    float4 bb = *(const float4*)&bias[n0 + tx * 4];
    #pragma unroll
    for (int i = 0; i < 4; i++) {
        int m = m0 + ty * 4 + i;
        float4 out;
        out.x = acc[i][0] + bb.x;
        out.y = acc[i][1] + bb.y;
        out.z = acc[i][2] + bb.z;
        out.w = acc[i][3] + bb.w;
        *(float4*)&g_proj[(size_t)m * PROJD + n0 + tx * 4] = out;
    }
}

// ============ Kernel 2: normalize + transpose to [i,t,c] layout ============
// input row r = (bs*T + t)*Q + q ; output row = (base + bs*Q + q)*T + t
__global__ void __launch_bounds__(256) normalize_kernel(int base)
{
    int warp = threadIdx.x >> 5;
    int lane = threadIdx.x & 31;
    int r = blockIdx.x * 8 + warp;          // 0..25599
    int q  = r % QQ;
    int tq = r / QQ;
    int t  = tq % TT;
    int bs = tq / TT;
    int i  = bs * QQ + q;
    int orow = (base + i) * TT + t;

    const float* src = &g_proj[(size_t)r * PROJD];
    float4 v0 = *(const float4*)&src[lane * 4];
    float4 v1 = *(const float4*)&src[128 + lane * 4];
    float s = v0.x*v0.x + v0.y*v0.y + v0.z*v0.z + v0.w*v0.w
            + v1.x*v1.x + v1.y*v1.y + v1.z*v1.z + v1.w*v1.w;
    s = warp_sum(s);
    float inv = 1.0f / sqrtf(s);
    v0.x*=inv; v0.y*=inv; v0.z*=inv; v0.w*=inv;
    v1.x*=inv; v1.y*=inv; v1.z*=inv; v1.w*=inv;
    float* dst = &g_neg[(size_t)orow * PROJD];
    *(float4*)&dst[lane * 4]       = v0;
    *(float4*)&dst[128 + lane * 4] = v1;
    if (lane == 0) g_nsq[orow] = s * inv * inv;
}

// ============ Kernel 3: per-i bridge prep (alpha, sigma, a, numer) ============
__global__ void __launch_bounds__(256) bridge_prep_kernel(const int* __restrict__ bridge)
{
    int warp = threadIdx.x >> 5;
    int lane = threadIdx.x & 31;
    int i = blockIdx.x * 8 + warp;        // 0..1599
    int bh = bridge[i * 3 + 0];
    int bp = bridge[i * 3 + 1];
    int bt = bridge[i * 3 + 2];
    float bhf = (float)bh, bpf = (float)bp, btf = (float)bt;
    float alpha = (bpf - bhf) / (btf - bhf);
    float sigma = alpha * (btf - bpf);
    float inv2s = 1.0f / (2.0f * sigma * sigma);

    const float* r0 = &g_neg[(size_t)(i * TT + bh) * PROJD];
    const float* r1 = &g_neg[(size_t)(i * TT + bp) * PROJD];
    const float* r2 = &g_neg[(size_t)(i * TT + bt) * PROJD];
    float oma = 1.0f - alpha;
    float xs = 0.0f, as = 0.0f;
    float av[8];
    #pragma unroll
    for (int h = 0; h < 2; h++) {
        int c = h * 128 + lane * 4;
        float4 a0 = *(const float4*)&r0[c];
        float4 a1 = *(const float4*)&r1[c];
        float4 a2 = *(const float4*)&r2[c];
        float g0[4] = {a0.x,a0.y,a0.z,a0.w};
        float g1[4] = {a1.x,a1.y,a1.z,a1.w};
        float g2[4] = {a2.x,a2.y,a2.z,a2.w};
        #pragma unroll
        for (int e = 0; e < 4; e++) {
            float aa = oma * g0[e] + alpha * g2[e];
            float x  = g1[e] - oma * g0[e] - alpha * g2[e];
            xs += x * x;
            as += aa * aa;
            av[h * 4 + e] = aa;
        }
    }
    xs = warp_sum(xs);
    as = warp_sum(as);
    float* adst = &g_a[(size_t)i * PROJD];
    *(float4*)&adst[lane * 4]       = make_float4(av[0], av[1], av[2], av[3]);
    *(float4*)&adst[128 + lane * 4] = make_float4(av[4], av[5], av[6], av[7]);
    if (lane == 0) {
        g_bp[i]    = bp;
        g_inv2s[i] = inv2s;
        g_asq[i]   = as;
        g_numer[i] = expf(-xs * inv2s);
    }
}

// ============ Kernel 4: bucket i's by bp value (counting sort) ============
__global__ void __launch_bounds__(256) bucket_kernel()
{
    __shared__ int hist[TT], off[TT];
    int tid = threadIdx.x;
    if (tid < TT) hist[tid] = 0;
    __syncthreads();
    for (int i = tid; i < NI; i += 256) atomicAdd(&hist[g_bp[i]], 1);
    __syncthreads();
    if (tid == 0) {
        int s = 0;
        for (int t = 0; t < TT; t++) { g_bucket_start[t] = s; off[t] = s; s += hist[t]; }
        g_bucket_start[TT] = s;
    }
    __syncthreads();
    for (int i = tid; i < NI; i += 256) {
        int pos = atomicAdd(&off[g_bp[i]], 1);
        g_order[pos] = i;
    }
}

// ============ Kernel 5: bucketed dist GEMM ============
// For bucket t: dist[i,j] = -(nsq[j,t] - 2*(a_i . neg[j,t]) + asq_i) * inv2s_i
#define DTI 32
#define DTJ 64
#define DTK 32
__global__ void __launch_bounds__(256) dist_gemm_kernel()
{
    int t = blockIdx.y;
    int start = g_bucket_start[t];
    int cnt   = g_bucket_start[t + 1] - start;
    if (cnt == 0) return;
    int j0 = blockIdx.x * DTJ;

    __shared__ float As[DTI][DTK + 1];
    __shared__ float Bs[DTJ][DTK + 1];
    __shared__ int   sidx[DTI];

    int tid = threadIdx.x;
    int tx = tid & 31;   // j dir x2
    int ty = tid >> 5;   // i dir x4

    for (int ic = 0; ic < cnt; ic += DTI) {
        int cc = min(DTI, cnt - ic);
        if (tid < DTI) sidx[tid] = (tid < cc) ? g_order[start + ic + tid] : 0;
        __syncthreads();

        float acc[4][2] = {};
        for (int k0 = 0; k0 < PROJD; k0 += DTK) {
            // load A: 32 rows x 32 k = 256 float4 (1/thread)
            {
                int row = tid >> 3;
                int kq  = (tid & 7) * 4;
                float4 v = make_float4(0.f, 0.f, 0.f, 0.f);
                if (row < cc)
                    v = *(const float4*)&g_a[(size_t)sidx[row] * PROJD + k0 + kq];
                As[row][kq + 0] = v.x; As[row][kq + 1] = v.y;
                As[row][kq + 2] = v.z; As[row][kq + 3] = v.w;
            }
            // load B: 64 rows x 32 k = 512 float4 (2/thread)
            #pragma unroll
            for (int l = 0; l < 2; l++) {
                int fl = tid * 2 + l;
                int row = fl >> 3;
                int kq  = (fl & 7) * 4;
                float4 v = *(const float4*)&g_neg[(size_t)((j0 + row) * TT + t) * PROJD + k0 + kq];
                Bs[row][kq + 0] = v.x; Bs[row][kq + 1] = v.y;
                Bs[row][kq + 2] = v.z; Bs[row][kq + 3] = v.w;
            }
            __syncthreads();
            #pragma unroll
            for (int kk = 0; kk < DTK; kk++) {
                float ar[4], br[2];
                #pragma unroll
                for (int u = 0; u < 4; u++) ar[u] = As[ty * 4 + u][kk];
                #pragma unroll
                for (int v = 0; v < 2; v++) br[v] = Bs[tx * 2 + v][kk];
                #pragma unroll
                for (int u = 0; u < 4; u++)
                    #pragma unroll
                    for (int v = 0; v < 2; v++)
                        acc[u][v] = fmaf(ar[u], br[v], acc[u][v]);
            }
            __syncthreads();
        }
        #pragma unroll
        for (int u = 0; u < 4; u++) {
            int r = ty * 4 + u;
            if (r < cc) {
                int i = sidx[r];
                float asqi = g_asq[i];
                float is2  = g_inv2s[i];
                #pragma unroll
                for (int v = 0; v < 2; v++) {
                    int j = j0 + tx * 2 + v;
                    float d = -(g_nsq[j * TT + t] - 2.0f * acc[u][v] + asqi) * is2;
                    if (j == i) { g_self[i] = d; d = -10000.0f; }
                    g_dist[(size_t)i * NNEG + j] = d;
                }
            }
        }
        __syncthreads();
    }
}

// ============ Kernel 6: per-row top-5 + self -> brownian term ============
__global__ void __launch_bounds__(256) topk_kernel()
{
    int i = blockIdx.x;
    __shared__ float cand[256 * 5];
    float t5[5] = {-1e30f, -1e30f, -1e30f, -1e30f, -1e30f};
    const float* row = &g_dist[(size_t)i * NNEG];
    for (int j = threadIdx.x; j < NNEG; j += 256) {
        float v = row[j];
        if (v > t5[4]) {
            int k = 4;
            while (k > 0 && v > t5[k - 1]) { t5[k] = t5[k - 1]; k--; }
            t5[k] = v;
        }
    }
    #pragma unroll
    for (int k = 0; k < 5; k++) cand[threadIdx.x * 5 + k] = t5[k];
    __syncthreads();
    if (threadIdx.x == 0) {
        float best[5] = {-1e30f, -1e30f, -1e30f, -1e30f, -1e30f};
        for (int m = 0; m < 256 * 5; m++) {
            float v = cand[m];
            if (v > best[4]) {
                int k = 4;
                while (k > 0 && v > best[k - 1]) { best[k] = best[k - 1]; k--; }
                best[k] = v;
            }
        }
        float deno = expf(g_self[i]);
        #pragma unroll
        for (int k = 0; k < 5; k++) deno += expf(best[k]);
        g_brown[i] = g_numer[i] / deno;
    }
}

// ============ Kernel 7: head-tail softplus term ============
__global__ void __launch_bounds__(256) headtail_kernel()
{
    int warp = threadIdx.x >> 5;
    int lane = threadIdx.x & 31;
    int i = blockIdx.x * 8 + warp;
    const float* r0 = &g_neg[(size_t)(i * TT + 0) * PROJD];
    const float* r1 = &g_neg[(size_t)(i * TT + (TT - 1)) * PROJD];
    float s = 0.0f;
    #pragma unroll
    for (int h = 0; h < 2; h++) {
        int c = h * 128 + lane * 4;
        float4 a = *(const float4*)&r0[c];
        float4 b = *(const float4*)&r1[c];
        s += a.x * b.x + a.y * b.y + a.z * b.z + a.w * b.w;
    }
    s = warp_sum(s);
    if (lane == 0) {
        float z = 0.3f - s;
        g_ht[i] = log1pf(expf(z));
    }
}

// ============ Kernel 8: deterministic final reduction ============
__global__ void __launch_bounds__(256) final_kernel(float* __restrict__ out)
{
    __shared__ float sb[256], sh[256];
    int tid = threadIdx.x;
    float b = 0.0f, h = 0.0f;
    for (int i = tid; i < NI; i += 256) { b += g_brown[i]; h += g_ht[i]; }
    sb[tid] = b; sh[tid] = h;
    __syncthreads();
    for (int s = 128; s > 0; s >>= 1) {
        if (tid < s) { sb[tid] += sb[tid + s]; sh[tid] += sh[tid + s]; }
        __syncthreads();
    }
    if (tid == 0) {
        out[0] = sb[0] / (float)NI;
        out[1] = sh[0] / (float)NI;
    }
}

// ==================== launch ====================
extern "C" void kernel_launch(void* const* d_in, const int* in_sizes, int n_in,
                              void* d_out, int out_size)
{
    const float* fe     = (const float*)d_in[0];
    const float* ofe    = (const float*)d_in[1];
    const float* W      = (const float*)d_in[2];
    const float* bias   = (const float*)d_in[3];
    const int*   bridge = (const int*)d_in[4];
    float* out = (float*)d_out;

    dim3 ggrid(PROJD / GBN, MROWS / GBM);   // (4, 400)

    gemm_bias_kernel<<<ggrid, 256>>>(fe, W, bias);
    normalize_kernel<<<MROWS / 8, 256>>>(0);
    gemm_bias_kernel<<<ggrid, 256>>>(ofe, W, bias);
    normalize_kernel<<<MROWS / 8, 256>>>(NI);

    bridge_prep_kernel<<<NI / 8, 256>>>(bridge);
    bucket_kernel<<<1, 256>>>();
    dist_gemm_kernel<<<dim3(NNEG / DTJ, TT), 256>>>();
    topk_kernel<<<NI, 256>>>();
    headtail_kernel<<<NI / 8, 256>>>();
    final_kernel<<<1, 256>>>(out);
}

// round 4
// speedup vs baseline: 1.4185x; 1.4185x over previous
#include <cstdint>
#include <stdint.h>
#include <cuda_runtime.h>
#include <cuda_bf16.h>
#include <mma.h>
#include <math.h>

using namespace nvcuda;

#define BSZ   16
#define TT    16
#define QQ    100
#define HIDD  256
#define PROJD 256
#define NI    1600    // BS*Q
#define MROWS 25600   // BS*T*Q
#define NNEG  3200

// -------- scratch (device globals; no allocation allowed) --------
__device__ float g_neg[NNEG * TT * PROJD];       // 52.4 MB  [j, t, c]
__device__ float g_nsq[NNEG * TT];               // sum(neg^2) per (j,t)
__device__ float g_a[NI * PROJD];
__device__ float g_asq[NI];
__device__ float g_numer[NI];
__device__ float g_inv2s[NI];
__device__ int   g_bp[NI];
__device__ float g_dist[NI * NNEG];              // 20.5 MB
__device__ float g_self[NI];
__device__ int   g_bucket_start[TT + 1];
__device__ int   g_order[NI];
__device__ float g_brown[NI];
__device__ float g_ht[NI];
__device__ __nv_bfloat16 g_wt_hi[PROJD * HIDD];  // W^T split-hi  [n][k]
__device__ __nv_bfloat16 g_wt_lo[PROJD * HIDD];  // W^T split-lo  [n][k]

__device__ __forceinline__ float warp_sum(float v) {
    #pragma unroll
    for (int o = 16; o > 0; o >>= 1) v += __shfl_xor_sync(0xffffffffu, v, o);
    return v;
}

// ============ Kernel 0: W -> W^T split into bf16 hi/lo ============
__global__ void __launch_bounds__(256) convert_w_kernel(const float* __restrict__ W)
{
    int k = blockIdx.x;      // 0..255 (HID)
    int n = threadIdx.x;     // 0..255 (PROJ)
    float v = W[k * PROJD + n];
    __nv_bfloat16 h = __float2bfloat16(v);
    g_wt_hi[n * HIDD + k] = h;
    g_wt_lo[n * HIDD + k] = __float2bfloat16(v - __bfloat162float(h));
}

// ============ Kernel 1: wmma bf16-split projection + bias + normalize + transpose ============
// CTA: 128 rows x 256 cols, K=256 in 4 chunks of 64.
// 8 warps arranged 4(M) x 2(N): warp tile 32 x 128.
// C = Ahi*Bhi + Alo*Bhi + Ahi*Blo  (fp32 accum; lo*lo dropped).
#define KC   64
#define LDA  72      // A tile leading dim (elements), 144B rows
#define LDB  72      // B tile leading dim (col-major stride per n), 144B
#define STG_LD 260   // output stage leading dim (floats)

#define OFF_BIAS  0
#define OFF_U     1024
#define OFF_A_HI  (OFF_U)                       // 128*72*2        = 18432
#define OFF_A_LO  (OFF_A_HI + 128 * LDA * 2)    // +18432
#define OFF_B_HI  (OFF_A_LO + 128 * LDA * 2)    // 256*72*2        = 36864
#define OFF_B_LO  (OFF_B_HI + 256 * LDB * 2)
#define TILES_END (OFF_B_LO + 256 * LDB * 2)    // 1024 + 110592
#define STG_BYTES (128 * STG_LD * 4)            // 133120
#define PROJ_SMEM ((OFF_U + STG_BYTES) > TILES_END ? (OFF_U + STG_BYTES) : TILES_END)

__global__ void __launch_bounds__(256, 1) proj_mma_kernel(
    const float* __restrict__ fe, const float* __restrict__ ofe,
    const float* __restrict__ bias)
{
    extern __shared__ char smem_raw[];
    float* bias_s = (float*)(smem_raw + OFF_BIAS);
    __nv_bfloat16* Ah = (__nv_bfloat16*)(smem_raw + OFF_A_HI);
    __nv_bfloat16* Al = (__nv_bfloat16*)(smem_raw + OFF_A_LO);
    __nv_bfloat16* Bh = (__nv_bfloat16*)(smem_raw + OFF_B_HI);
    __nv_bfloat16* Bl = (__nv_bfloat16*)(smem_raw + OFF_B_LO);
    float* stage = (float*)(smem_raw + OFF_U);

    int tid  = threadIdx.x;
    int wid  = tid >> 5;
    int lane = tid & 31;

    int b = blockIdx.x;                 // 0..399
    const float* A = (b < 200) ? fe : ofe;
    int base = (b < 200) ? 0 : NI;
    int m0   = (b % 200) * 128;

    bias_s[tid] = bias[tid];

    // warp position: 4 M x 2 N
    int wm = wid >> 1;                  // 0..3 -> rows wm*32
    int wn = wid & 1;                   // 0..1 -> cols wn*128

    wmma::fragment<wmma::accumulator, 16, 16, 16, float> acc[2][8];
    #pragma unroll
    for (int mt = 0; mt < 2; mt++)
        #pragma unroll
        for (int nt = 0; nt < 8; nt++)
            wmma::fill_fragment(acc[mt][nt], 0.0f);

    for (int c = 0; c < 4; c++) {
        int k0 = c * KC;
        __syncthreads();   // protect tiles from previous iteration's consumers
        // ---- load & split A chunk: 128 rows x 64 fp32 -> hi/lo bf16 ----
        #pragma unroll
        for (int it = 0; it < 8; it++) {
            int flat = it * 256 + tid;
            int row  = flat >> 4;          // 0..127
            int j    = flat & 15;          // k quad
            float4 v = *(const float4*)&A[(size_t)(m0 + row) * HIDD + k0 + j * 4];
            __nv_bfloat16 h0 = __float2bfloat16(v.x);
            __nv_bfloat16 h1 = __float2bfloat16(v.y);
            __nv_bfloat16 h2 = __float2bfloat16(v.z);
            __nv_bfloat16 h3 = __float2bfloat16(v.w);
            __nv_bfloat16 l0 = __float2bfloat16(v.x - __bfloat162float(h0));
            __nv_bfloat16 l1 = __float2bfloat16(v.y - __bfloat162float(h1));
            __nv_bfloat16 l2 = __float2bfloat16(v.z - __bfloat162float(h2));
            __nv_bfloat16 l3 = __float2bfloat16(v.w - __bfloat162float(h3));
            int o = row * LDA + j * 4;
            *(__nv_bfloat162*)&Ah[o]     = __nv_bfloat162{h0, h1};
            *(__nv_bfloat162*)&Ah[o + 2] = __nv_bfloat162{h2, h3};
            *(__nv_bfloat162*)&Al[o]     = __nv_bfloat162{l0, l1};
            *(__nv_bfloat162*)&Al[o + 2] = __nv_bfloat162{l2, l3};
        }
        // ---- load B chunk (pre-split): [n][k_local], col-major for wmma ----
        #pragma unroll
        for (int it = 0; it < 8; it++) {
            int flat = it * 256 + tid;
            int n = flat >> 3;             // 0..255
            int u = flat & 7;              // k octet
            uint4 vh = *(const uint4*)&g_wt_hi[(size_t)n * HIDD + k0 + u * 8];
            uint4 vl = *(const uint4*)&g_wt_lo[(size_t)n * HIDD + k0 + u * 8];
            *(uint4*)&Bh[n * LDB + u * 8] = vh;
            *(uint4*)&Bl[n * LDB + u * 8] = vl;
        }
        __syncthreads();

        // ---- compute ----
        #pragma unroll
        for (int kt = 0; kt < KC / 16; kt++) {
            wmma::fragment<wmma::matrix_a, 16, 16, 16, __nv_bfloat16, wmma::row_major> ah[2], al[2];
            #pragma unroll
            for (int mt = 0; mt < 2; mt++) {
                int row0 = wm * 32 + mt * 16;
                wmma::load_matrix_sync(ah[mt], Ah + row0 * LDA + kt * 16, LDA);
                wmma::load_matrix_sync(al[mt], Al + row0 * LDA + kt * 16, LDA);
            }
            #pragma unroll
            for (int nt = 0; nt < 8; nt++) {
                int n0 = wn * 128 + nt * 16;
                wmma::fragment<wmma::matrix_b, 16, 16, 16, __nv_bfloat16, wmma::col_major> bh, bl;
                wmma::load_matrix_sync(bh, Bh + n0 * LDB + kt * 16, LDB);
                wmma::load_matrix_sync(bl, Bl + n0 * LDB + kt * 16, LDB);
                #pragma unroll
                for (int mt = 0; mt < 2; mt++) {
                    wmma::mma_sync(acc[mt][nt], ah[mt], bh, acc[mt][nt]);
                    wmma::mma_sync(acc[mt][nt], al[mt], bh, acc[mt][nt]);
                    wmma::mma_sync(acc[mt][nt], ah[mt], bl, acc[mt][nt]);
                }
            }
        }
    }

    // ---- stage results to smem (overlaps tiles; sync first) ----
    __syncthreads();
    #pragma unroll
    for (int mt = 0; mt < 2; mt++) {
        int row0 = wm * 32 + mt * 16;
        #pragma unroll
        for (int nt = 0; nt < 8; nt++) {
            int n0 = wn * 128 + nt * 16;
            wmma::store_matrix_sync(stage + row0 * STG_LD + n0, acc[mt][nt],
                                    STG_LD, wmma::mem_row_major);
        }
    }
    __syncthreads();

    // ---- epilogue: bias + L2-normalize + transposed write ----
    // warp w handles rows [w*16, w*16+16)
    for (int rr = 0; rr < 16; rr++) {
        int r = wid * 16 + rr;
        float v[8];
        float ss = 0.0f;
        #pragma unroll
        for (int u = 0; u < 8; u++) {
            int cidx = lane + 32 * u;
            float x = stage[r * STG_LD + cidx] + bias_s[cidx];
            v[u] = x;
            ss += x * x;
        }
        ss = warp_sum(ss);
        float inv = rsqrtf(ss);
        int m = m0 + r;
        int q = m % QQ;
        int t = (m / QQ) % TT;
        int bs = m / (QQ * TT);
        int orow = (base + bs * QQ + q) * TT + t;
        #pragma unroll
        for (int u = 0; u < 8; u++)
            g_neg[(size_t)orow * PROJD + lane + 32 * u] = v[u] * inv;
        if (lane == 0) g_nsq[orow] = ss * inv * inv;
    }
}

// ============ Kernel 3: per-i bridge prep (alpha, sigma, a, numer) ============
__global__ void __launch_bounds__(256) bridge_prep_kernel(const int* __restrict__ bridge)
{
    int warp = threadIdx.x >> 5;
    int lane = threadIdx.x & 31;
    int i = blockIdx.x * 8 + warp;        // 0..1599
    int bh = bridge[i * 3 + 0];
    int bp = bridge[i * 3 + 1];
    int bt = bridge[i * 3 + 2];
    float bhf = (float)bh, bpf = (float)bp, btf = (float)bt;
    float alpha = (bpf - bhf) / (btf - bhf);
    float sigma = alpha * (btf - bpf);
    float inv2s = 1.0f / (2.0f * sigma * sigma);

    const float* r0 = &g_neg[(size_t)(i * TT + bh) * PROJD];
    const float* r1 = &g_neg[(size_t)(i * TT + bp) * PROJD];
    const float* r2 = &g_neg[(size_t)(i * TT + bt) * PROJD];
    float oma = 1.0f - alpha;
    float xs = 0.0f, as = 0.0f;
    float av[8];
    #pragma unroll
    for (int h = 0; h < 2; h++) {
        int c = h * 128 + lane * 4;
        float4 a0 = *(const float4*)&r0[c];
        float4 a1 = *(const float4*)&r1[c];
        float4 a2 = *(const float4*)&r2[c];
        float g0[4] = {a0.x,a0.y,a0.z,a0.w};
        float g1[4] = {a1.x,a1.y,a1.z,a1.w};
        float g2[4] = {a2.x,a2.y,a2.z,a2.w};
        #pragma unroll
        for (int e = 0; e < 4; e++) {
            float aa = oma * g0[e] + alpha * g2[e];
            float x  = g1[e] - oma * g0[e] - alpha * g2[e];
            xs += x * x;
            as += aa * aa;
            av[h * 4 + e] = aa;
        }
    }
    xs = warp_sum(xs);
    as = warp_sum(as);
    float* adst = &g_a[(size_t)i * PROJD];
    *(float4*)&adst[lane * 4]       = make_float4(av[0], av[1], av[2], av[3]);
    *(float4*)&adst[128 + lane * 4] = make_float4(av[4], av[5], av[6], av[7]);
    if (lane == 0) {
        g_bp[i]    = bp;
        g_inv2s[i] = inv2s;
        g_asq[i]   = as;
        g_numer[i] = expf(-xs * inv2s);
    }
}

// ============ Kernel 4: bucket i's by bp value (counting sort) ============
__global__ void __launch_bounds__(256) bucket_kernel()
{
    __shared__ int hist[TT], off[TT];
    int tid = threadIdx.x;
    if (tid < TT) hist[tid] = 0;
    __syncthreads();
    for (int i = tid; i < NI; i += 256) atomicAdd(&hist[g_bp[i]], 1);
    __syncthreads();
    if (tid == 0) {
        int s = 0;
        for (int t = 0; t < TT; t++) { g_bucket_start[t] = s; off[t] = s; s += hist[t]; }
        g_bucket_start[TT] = s;
    }
    __syncthreads();
    for (int i = tid; i < NI; i += 256) {
        int pos = atomicAdd(&off[g_bp[i]], 1);
        g_order[pos] = i;
    }
}

// ============ Kernel 5: bucketed dist GEMM ============
#define DTI 32
#define DTJ 64
#define DTK 32
__global__ void __launch_bounds__(256) dist_gemm_kernel()
{
    int t = blockIdx.y;
    int start = g_bucket_start[t];
    int cnt   = g_bucket_start[t + 1] - start;
    if (cnt == 0) return;
    int j0 = blockIdx.x * DTJ;

    __shared__ float As[DTI][DTK + 1];
    __shared__ float Bs[DTJ][DTK + 1];
    __shared__ int   sidx[DTI];

    int tid = threadIdx.x;
    int tx = tid & 31;   // j dir x2
    int ty = tid >> 5;   // i dir x4

    for (int ic = 0; ic < cnt; ic += DTI) {
        int cc = min(DTI, cnt - ic);
        if (tid < DTI) sidx[tid] = (tid < cc) ? g_order[start + ic + tid] : 0;
        __syncthreads();

        float acc[4][2] = {};
        for (int k0 = 0; k0 < PROJD; k0 += DTK) {
            {
                int row = tid >> 3;
                int kq  = (tid & 7) * 4;
                float4 v = make_float4(0.f, 0.f, 0.f, 0.f);
                if (row < cc)
                    v = *(const float4*)&g_a[(size_t)sidx[row] * PROJD + k0 + kq];
                As[row][kq + 0] = v.x; As[row][kq + 1] = v.y;
                As[row][kq + 2] = v.z; As[row][kq + 3] = v.w;
            }
            #pragma unroll
            for (int l = 0; l < 2; l++) {
                int fl = tid * 2 + l;
                int row = fl >> 3;
                int kq  = (fl & 7) * 4;
                float4 v = *(const float4*)&g_neg[(size_t)((j0 + row) * TT + t) * PROJD + k0 + kq];
                Bs[row][kq + 0] = v.x; Bs[row][kq + 1] = v.y;
                Bs[row][kq + 2] = v.z; Bs[row][kq + 3] = v.w;
            }
            __syncthreads();
            #pragma unroll
            for (int kk = 0; kk < DTK; kk++) {
                float ar[4], br[2];
                #pragma unroll
                for (int u = 0; u < 4; u++) ar[u] = As[ty * 4 + u][kk];
                #pragma unroll
                for (int v = 0; v < 2; v++) br[v] = Bs[tx * 2 + v][kk];
                #pragma unroll
                for (int u = 0; u < 4; u++)
                    #pragma unroll
                    for (int v = 0; v < 2; v++)
                        acc[u][v] = fmaf(ar[u], br[v], acc[u][v]);
            }
            __syncthreads();
        }
        #pragma unroll
        for (int u = 0; u < 4; u++) {
            int r = ty * 4 + u;
            if (r < cc) {
                int i = sidx[r];
                float asqi = g_asq[i];
                float is2  = g_inv2s[i];
                #pragma unroll
                for (int v = 0; v < 2; v++) {
                    int j = j0 + tx * 2 + v;
                    float d = -(g_nsq[j * TT + t] - 2.0f * acc[u][v] + asqi) * is2;
                    if (j == i) { g_self[i] = d; d = -10000.0f; }
                    g_dist[(size_t)i * NNEG + j] = d;
                }
            }
        }
        __syncthreads();
    }
}

// ============ Kernel 6: per-row top-5 + self -> brownian term ============
__global__ void __launch_bounds__(256) topk_kernel()
{
    int i = blockIdx.x;
    __shared__ float cand[256 * 5];
    float t5[5] = {-1e30f, -1e30f, -1e30f, -1e30f, -1e30f};
    const float* row = &g_dist[(size_t)i * NNEG];
    for (int j = threadIdx.x; j < NNEG; j += 256) {
        float v = row[j];
        if (v > t5[4]) {
            int k = 4;
            while (k > 0 && v > t5[k - 1]) { t5[k] = t5[k - 1]; k--; }
            t5[k] = v;
        }
    }
    #pragma unroll
    for (int k = 0; k < 5; k++) cand[threadIdx.x * 5 + k] = t5[k];
    __syncthreads();
    if (threadIdx.x == 0) {
        float best[5] = {-1e30f, -1e30f, -1e30f, -1e30f, -1e30f};
        for (int m = 0; m < 256 * 5; m++) {
            float v = cand[m];
            if (v > best[4]) {
                int k = 4;
                while (k > 0 && v > best[k - 1]) { best[k] = best[k - 1]; k--; }
                best[k] = v;
            }
        }
        float deno = expf(g_self[i]);
        #pragma unroll
        for (int k = 0; k < 5; k++) deno += expf(best[k]);
        g_brown[i] = g_numer[i] / deno;
    }
}

// ============ Kernel 7: head-tail softplus term ============
__global__ void __launch_bounds__(256) headtail_kernel()
{
    int warp = threadIdx.x >> 5;
    int lane = threadIdx.x & 31;
    int i = blockIdx.x * 8 + warp;
    const float* r0 = &g_neg[(size_t)(i * TT + 0) * PROJD];
    const float* r1 = &g_neg[(size_t)(i * TT + (TT - 1)) * PROJD];
    float s = 0.0f;
    #pragma unroll
    for (int h = 0; h < 2; h++) {
        int c = h * 128 + lane * 4;
        float4 a = *(const float4*)&r0[c];
        float4 b = *(const float4*)&r1[c];
        s += a.x * b.x + a.y * b.y + a.z * b.z + a.w * b.w;
    }
    s = warp_sum(s);
    if (lane == 0) {
        float z = 0.3f - s;
        g_ht[i] = log1pf(expf(z));
    }
}

// ============ Kernel 8: deterministic final reduction ============
__global__ void __launch_bounds__(256) final_kernel(float* __restrict__ out)
{
    __shared__ float sb[256], sh[256];
    int tid = threadIdx.x;
    float b = 0.0f, h = 0.0f;
    for (int i = tid; i < NI; i += 256) { b += g_brown[i]; h += g_ht[i]; }
    sb[tid] = b; sh[tid] = h;
    __syncthreads();
    for (int s = 128; s > 0; s >>= 1) {
        if (tid < s) { sb[tid] += sb[tid + s]; sh[tid] += sh[tid + s]; }
        __syncthreads();
    }
    if (tid == 0) {
        out[0] = sb[0] / (float)NI;
        out[1] = sh[0] / (float)NI;
    }
}

// ==================== launch ====================
extern "C" void kernel_launch(void* const* d_in, const int* in_sizes, int n_in,
                              void* d_out, int out_size)
{
    const float* fe     = (const float*)d_in[0];
    const float* ofe    = (const float*)d_in[1];
    const float* W      = (const float*)d_in[2];
    const float* bias   = (const float*)d_in[3];
    const int*   bridge = (const int*)d_in[4];
    float* out = (float*)d_out;

    cudaFuncSetAttribute(proj_mma_kernel, cudaFuncAttributeMaxDynamicSharedMemorySize, PROJ_SMEM);

    convert_w_kernel<<<HIDD, PROJD>>>(W);
    proj_mma_kernel<<<400, 256, PROJ_SMEM>>>(fe, ofe, bias);

    bridge_prep_kernel<<<NI / 8, 256>>>(bridge);
    bucket_kernel<<<1, 256>>>();
    dist_gemm_kernel<<<dim3(NNEG / DTJ, TT), 256>>>();
    topk_kernel<<<NI, 256>>>();
    headtail_kernel<<<NI / 8, 256>>>();
    final_kernel<<<1, 256>>>(out);
}

// round 5
// speedup vs baseline: 1.5599x; 1.0996x over previous
#include <cstdint>
#include <stdint.h>
#include <cuda_runtime.h>
#include <cuda_bf16.h>
#include <mma.h>
#include <math.h>

using namespace nvcuda;

#define BSZ   16
#define TT    16
#define QQ    100
#define HIDD  256
#define PROJD 256
#define NI    1600    // BS*Q
#define MROWS 25600   // BS*T*Q
#define NNEG  3200

// -------- scratch (device globals; no allocation allowed) --------
__device__ __nv_bfloat16 g_neg_h[NNEG * TT * PROJD];   // 26.2 MB  [j, t, c] hi
__device__ __nv_bfloat16 g_neg_l[NNEG * TT * PROJD];   // 26.2 MB  lo
__device__ float g_nsq[NNEG * TT];                     // sum(neg^2) per (j,t)
__device__ __nv_bfloat16 g_a_h[NI * PROJD];
__device__ __nv_bfloat16 g_a_l[NI * PROJD];
__device__ float g_asq[NI];
__device__ float g_numer[NI];
__device__ float g_inv2s[NI];
__device__ int   g_bp[NI];
__device__ float g_dist[NI * NNEG];              // 20.5 MB
__device__ float g_self[NI];
__device__ int   g_bucket_start[TT + 1];
__device__ int   g_order[NI];
__device__ float g_brown[NI];
__device__ float g_ht[NI];
__device__ __nv_bfloat16 g_wt_hi[PROJD * HIDD];  // W^T split-hi  [n][k]
__device__ __nv_bfloat16 g_wt_lo[PROJD * HIDD];  // W^T split-lo  [n][k]

__device__ __forceinline__ float warp_sum(float v) {
    #pragma unroll
    for (int o = 16; o > 0; o >>= 1) v += __shfl_xor_sync(0xffffffffu, v, o);
    return v;
}

// reconstruct 4 floats from hi/lo bf16 arrays at index idx (8-byte aligned)
__device__ __forceinline__ void ld_rec4(const __nv_bfloat16* __restrict__ h,
                                        const __nv_bfloat16* __restrict__ l,
                                        size_t idx, float* out) {
    __nv_bfloat162 h0 = *(const __nv_bfloat162*)&h[idx];
    __nv_bfloat162 h1 = *(const __nv_bfloat162*)&h[idx + 2];
    __nv_bfloat162 l0 = *(const __nv_bfloat162*)&l[idx];
    __nv_bfloat162 l1 = *(const __nv_bfloat162*)&l[idx + 2];
    out[0] = __bfloat162float(h0.x) + __bfloat162float(l0.x);
    out[1] = __bfloat162float(h0.y) + __bfloat162float(l0.y);
    out[2] = __bfloat162float(h1.x) + __bfloat162float(l1.x);
    out[3] = __bfloat162float(h1.y) + __bfloat162float(l1.y);
}

// ============ Kernel 0: W -> W^T split into bf16 hi/lo ============
__global__ void __launch_bounds__(256) convert_w_kernel(const float* __restrict__ W)
{
    int k = blockIdx.x;      // 0..255 (HID)
    int n = threadIdx.x;     // 0..255 (PROJ)
    float v = W[k * PROJD + n];
    __nv_bfloat16 h = __float2bfloat16(v);
    g_wt_hi[n * HIDD + k] = h;
    g_wt_lo[n * HIDD + k] = __float2bfloat16(v - __bfloat162float(h));
}

// ============ Kernel 1: wmma bf16-split projection + bias + normalize + transpose ============
#define KC   64
#define LDA  72
#define LDB  72
#define STG_LD 260

#define OFF_BIAS  0
#define OFF_U     1024
#define OFF_A_HI  (OFF_U)
#define OFF_A_LO  (OFF_A_HI + 128 * LDA * 2)
#define OFF_B_HI  (OFF_A_LO + 128 * LDA * 2)
#define OFF_B_LO  (OFF_B_HI + 256 * LDB * 2)
#define TILES_END (OFF_B_LO + 256 * LDB * 2)
#define STG_BYTES (128 * STG_LD * 4)
#define PROJ_SMEM ((OFF_U + STG_BYTES) > TILES_END ? (OFF_U + STG_BYTES) : TILES_END)

__global__ void __launch_bounds__(256, 1) proj_mma_kernel(
    const float* __restrict__ fe, const float* __restrict__ ofe,
    const float* __restrict__ bias)
{
    extern __shared__ char smem_raw[];
    float* bias_s = (float*)(smem_raw + OFF_BIAS);
    __nv_bfloat16* Ah = (__nv_bfloat16*)(smem_raw + OFF_A_HI);
    __nv_bfloat16* Al = (__nv_bfloat16*)(smem_raw + OFF_A_LO);
    __nv_bfloat16* Bh = (__nv_bfloat16*)(smem_raw + OFF_B_HI);
    __nv_bfloat16* Bl = (__nv_bfloat16*)(smem_raw + OFF_B_LO);
    float* stage = (float*)(smem_raw + OFF_U);

    int tid  = threadIdx.x;
    int wid  = tid >> 5;
    int lane = tid & 31;

    int b = blockIdx.x;
    const float* A = (b < 200) ? fe : ofe;
    int base = (b < 200) ? 0 : NI;
    int m0   = (b % 200) * 128;

    bias_s[tid] = bias[tid];

    int wm = wid >> 1;
    int wn = wid & 1;

    wmma::fragment<wmma::accumulator, 16, 16, 16, float> acc[2][8];
    #pragma unroll
    for (int mt = 0; mt < 2; mt++)
        #pragma unroll
        for (int nt = 0; nt < 8; nt++)
            wmma::fill_fragment(acc[mt][nt], 0.0f);

    for (int c = 0; c < 4; c++) {
        int k0 = c * KC;
        __syncthreads();
        #pragma unroll
        for (int it = 0; it < 8; it++) {
            int flat = it * 256 + tid;
            int row  = flat >> 4;
            int j    = flat & 15;
            float4 v = *(const float4*)&A[(size_t)(m0 + row) * HIDD + k0 + j * 4];
            __nv_bfloat16 h0 = __float2bfloat16(v.x);
            __nv_bfloat16 h1 = __float2bfloat16(v.y);
            __nv_bfloat16 h2 = __float2bfloat16(v.z);
            __nv_bfloat16 h3 = __float2bfloat16(v.w);
            __nv_bfloat16 l0 = __float2bfloat16(v.x - __bfloat162float(h0));
            __nv_bfloat16 l1 = __float2bfloat16(v.y - __bfloat162float(h1));
            __nv_bfloat16 l2 = __float2bfloat16(v.z - __bfloat162float(h2));
            __nv_bfloat16 l3 = __float2bfloat16(v.w - __bfloat162float(h3));
            int o = row * LDA + j * 4;
            *(__nv_bfloat162*)&Ah[o]     = __nv_bfloat162{h0, h1};
            *(__nv_bfloat162*)&Ah[o + 2] = __nv_bfloat162{h2, h3};
            *(__nv_bfloat162*)&Al[o]     = __nv_bfloat162{l0, l1};
            *(__nv_bfloat162*)&Al[o + 2] = __nv_bfloat162{l2, l3};
        }
        #pragma unroll
        for (int it = 0; it < 8; it++) {
            int flat = it * 256 + tid;
            int n = flat >> 3;
            int u = flat & 7;
            uint4 vh = *(const uint4*)&g_wt_hi[(size_t)n * HIDD + k0 + u * 8];
            uint4 vl = *(const uint4*)&g_wt_lo[(size_t)n * HIDD + k0 + u * 8];
            *(uint4*)&Bh[n * LDB + u * 8] = vh;
            *(uint4*)&Bl[n * LDB + u * 8] = vl;
        }
        __syncthreads();

        #pragma unroll
        for (int kt = 0; kt < KC / 16; kt++) {
            wmma::fragment<wmma::matrix_a, 16, 16, 16, __nv_bfloat16, wmma::row_major> ah[2], al[2];
            #pragma unroll
            for (int mt = 0; mt < 2; mt++) {
                int row0 = wm * 32 + mt * 16;
                wmma::load_matrix_sync(ah[mt], Ah + row0 * LDA + kt * 16, LDA);
                wmma::load_matrix_sync(al[mt], Al + row0 * LDA + kt * 16, LDA);
            }
            #pragma unroll
            for (int nt = 0; nt < 8; nt++) {
                int n0 = wn * 128 + nt * 16;
                wmma::fragment<wmma::matrix_b, 16, 16, 16, __nv_bfloat16, wmma::col_major> bh, bl;
                wmma::load_matrix_sync(bh, Bh + n0 * LDB + kt * 16, LDB);
                wmma::load_matrix_sync(bl, Bl + n0 * LDB + kt * 16, LDB);
                #pragma unroll
                for (int mt = 0; mt < 2; mt++) {
                    wmma::mma_sync(acc[mt][nt], ah[mt], bh, acc[mt][nt]);
                    wmma::mma_sync(acc[mt][nt], al[mt], bh, acc[mt][nt]);
                    wmma::mma_sync(acc[mt][nt], ah[mt], bl, acc[mt][nt]);
                }
            }
        }
    }

    __syncthreads();
    #pragma unroll
    for (int mt = 0; mt < 2; mt++) {
        int row0 = wm * 32 + mt * 16;
        #pragma unroll
        for (int nt = 0; nt < 8; nt++) {
            int n0 = wn * 128 + nt * 16;
            wmma::store_matrix_sync(stage + row0 * STG_LD + n0, acc[mt][nt],
                                    STG_LD, wmma::mem_row_major);
        }
    }
    __syncthreads();

    // ---- epilogue: bias + L2-normalize + transposed bf16 hi/lo write ----
    for (int rr = 0; rr < 16; rr++) {
        int r = wid * 16 + rr;
        float v[8];
        float ss = 0.0f;
        #pragma unroll
        for (int u = 0; u < 8; u++) {
            int cidx = lane + 32 * u;
            float x = stage[r * STG_LD + cidx] + bias_s[cidx];
            v[u] = x;
            ss += x * x;
        }
        ss = warp_sum(ss);
        float inv = rsqrtf(ss);
        int m = m0 + r;
        int q = m % QQ;
        int t = (m / QQ) % TT;
        int bs = m / (QQ * TT);
        int orow = (base + bs * QQ + q) * TT + t;
        #pragma unroll
        for (int u = 0; u < 8; u++) {
            float x = v[u] * inv;
            __nv_bfloat16 h = __float2bfloat16(x);
            size_t o = (size_t)orow * PROJD + lane + 32 * u;
            g_neg_h[o] = h;
            g_neg_l[o] = __float2bfloat16(x - __bfloat162float(h));
        }
        if (lane == 0) g_nsq[orow] = ss * inv * inv;
    }
}

// ============ Kernel 3: per-i bridge prep (alpha, sigma, a, numer) ============
__global__ void __launch_bounds__(256) bridge_prep_kernel(const int* __restrict__ bridge)
{
    int warp = threadIdx.x >> 5;
    int lane = threadIdx.x & 31;
    int i = blockIdx.x * 8 + warp;        // 0..1599
    int bh = bridge[i * 3 + 0];
    int bp = bridge[i * 3 + 1];
    int bt = bridge[i * 3 + 2];
    float bhf = (float)bh, bpf = (float)bp, btf = (float)bt;
    float alpha = (bpf - bhf) / (btf - bhf);
    float sigma = alpha * (btf - bpf);
    float inv2s = 1.0f / (2.0f * sigma * sigma);

    size_t r0 = (size_t)(i * TT + bh) * PROJD;
    size_t r1 = (size_t)(i * TT + bp) * PROJD;
    size_t r2 = (size_t)(i * TT + bt) * PROJD;
    float oma = 1.0f - alpha;
    float xs = 0.0f, as = 0.0f;
    #pragma unroll
    for (int h = 0; h < 2; h++) {
        int c = h * 128 + lane * 4;
        float g0[4], g1[4], g2[4];
        ld_rec4(g_neg_h, g_neg_l, r0 + c, g0);
        ld_rec4(g_neg_h, g_neg_l, r1 + c, g1);
        ld_rec4(g_neg_h, g_neg_l, r2 + c, g2);
        #pragma unroll
        for (int e = 0; e < 4; e++) {
            float aa = oma * g0[e] + alpha * g2[e];
            float x  = g1[e] - oma * g0[e] - alpha * g2[e];
            xs += x * x;
            as += aa * aa;
            // write a-splits
            __nv_bfloat16 ah = __float2bfloat16(aa);
            size_t o = (size_t)i * PROJD + c + e;
            g_a_h[o] = ah;
            g_a_l[o] = __float2bfloat16(aa - __bfloat162float(ah));
        }
    }
    xs = warp_sum(xs);
    as = warp_sum(as);
    if (lane == 0) {
        g_bp[i]    = bp;
        g_inv2s[i] = inv2s;
        g_asq[i]   = as;
        g_numer[i] = expf(-xs * inv2s);
    }
}

// ============ Kernel 4: bucket i's by bp value (counting sort) ============
__global__ void __launch_bounds__(256) bucket_kernel()
{
    __shared__ int hist[TT], off[TT];
    int tid = threadIdx.x;
    if (tid < TT) hist[tid] = 0;
    __syncthreads();
    for (int i = tid; i < NI; i += 256) atomicAdd(&hist[g_bp[i]], 1);
    __syncthreads();
    if (tid == 0) {
        int s = 0;
        for (int t = 0; t < TT; t++) { g_bucket_start[t] = s; off[t] = s; s += hist[t]; }
        g_bucket_start[TT] = s;
    }
    __syncthreads();
    for (int i = tid; i < NI; i += 256) {
        int pos = atomicAdd(&off[g_bp[i]], 1);
        g_order[pos] = i;
    }
}

// ============ Kernel 5: bucketed dist GEMM (wmma bf16 split) ============
// CTA tile: 32 i x 64 j, K=256 resident. 8 warps = 2(i) x 4(j).
#define DLD   264    // padded k leading dim (elements)
#define DSTG  72     // stage leading dim (floats)
#define D_OFF_AH  0
#define D_OFF_AL  (D_OFF_AH + 32 * DLD * 2)     // 16896
#define D_OFF_BH  (D_OFF_AL + 32 * DLD * 2)
#define D_OFF_BL  (D_OFF_BH + 64 * DLD * 2)     // +33792
#define D_OFF_STG (D_OFF_BL + 64 * DLD * 2)
#define D_OFF_IDX (D_OFF_STG + 32 * DSTG * 4)
#define DIST_SMEM (D_OFF_IDX + 32 * 4)

__global__ void __launch_bounds__(256, 1) dist_mma_kernel()
{
    extern __shared__ char smem_raw[];
    __nv_bfloat16* Ah = (__nv_bfloat16*)(smem_raw + D_OFF_AH);
    __nv_bfloat16* Al = (__nv_bfloat16*)(smem_raw + D_OFF_AL);
    __nv_bfloat16* Bh = (__nv_bfloat16*)(smem_raw + D_OFF_BH);
    __nv_bfloat16* Bl = (__nv_bfloat16*)(smem_raw + D_OFF_BL);
    float* stage = (float*)(smem_raw + D_OFF_STG);
    int* sidx = (int*)(smem_raw + D_OFF_IDX);

    int t = blockIdx.y;
    int start = g_bucket_start[t];
    int cnt   = g_bucket_start[t + 1] - start;
    if (cnt == 0) return;
    int j0 = blockIdx.x * 64;

    int tid = threadIdx.x;
    int wid = tid >> 5;
    int wm = wid >> 2;    // 0..1  (i)
    int wn = wid & 3;     // 0..3  (j)

    // ---- load B tiles once: 64 j-rows x 256 k, hi/lo ----
    #pragma unroll
    for (int it = 0; it < 8; it++) {
        int flat = it * 256 + tid;          // 0..2047
        int jr = flat >> 5;                 // 0..63
        int k8 = flat & 31;                 // octet
        size_t src = (size_t)((j0 + jr) * TT + t) * PROJD + k8 * 8;
        *(uint4*)&Bh[jr * DLD + k8 * 8] = *(const uint4*)&g_neg_h[src];
        *(uint4*)&Bl[jr * DLD + k8 * 8] = *(const uint4*)&g_neg_l[src];
    }

    for (int ic = 0; ic < cnt; ic += 32) {
        int cc = min(32, cnt - ic);
        __syncthreads();     // protect A tiles + sidx + stage from prev iter readers
        if (tid < 32) sidx[tid] = (tid < cc) ? g_order[start + ic + tid] : g_order[start];
        __syncthreads();

        // ---- load A tiles: 32 rows x 256 k (gather) ----
        #pragma unroll
        for (int it = 0; it < 4; it++) {
            int flat = it * 256 + tid;      // 0..1023
            int r  = flat >> 5;             // 0..31
            int k8 = flat & 31;
            size_t src = (size_t)sidx[r] * PROJD + k8 * 8;
            *(uint4*)&Ah[r * DLD + k8 * 8] = *(const uint4*)&g_a_h[src];
            *(uint4*)&Al[r * DLD + k8 * 8] = *(const uint4*)&g_a_l[src];
        }
        __syncthreads();

        // ---- compute: warp tile 16x16, K=256 ----
        wmma::fragment<wmma::accumulator, 16, 16, 16, float> acc;
        wmma::fill_fragment(acc, 0.0f);
        #pragma unroll
        for (int kt = 0; kt < 16; kt++) {
            wmma::fragment<wmma::matrix_a, 16, 16, 16, __nv_bfloat16, wmma::row_major> ah, al;
            wmma::fragment<wmma::matrix_b, 16, 16, 16, __nv_bfloat16, wmma::col_major> bh, bl;
            wmma::load_matrix_sync(ah, Ah + (wm * 16) * DLD + kt * 16, DLD);
            wmma::load_matrix_sync(al, Al + (wm * 16) * DLD + kt * 16, DLD);
            wmma::load_matrix_sync(bh, Bh + (wn * 16) * DLD + kt * 16, DLD);
            wmma::load_matrix_sync(bl, Bl + (wn * 16) * DLD + kt * 16, DLD);
            wmma::mma_sync(acc, ah, bh, acc);
            wmma::mma_sync(acc, al, bh, acc);
            wmma::mma_sync(acc, ah, bl, acc);
        }
        wmma::store_matrix_sync(stage + (wm * 16) * DSTG + wn * 16, acc,
                                DSTG, wmma::mem_row_major);
        __syncthreads();

        // ---- epilogue: 8 elements per thread ----
        int r  = tid >> 3;                  // 0..31
        int c0 = (tid & 7) * 8;
        if (r < cc) {
            int i = sidx[r];
            float asqi = g_asq[i];
            float is2  = g_inv2s[i];
            #pragma unroll
            for (int u = 0; u < 8; u++) {
                int j = j0 + c0 + u;
                float cross = stage[r * DSTG + c0 + u];
                float d = -(g_nsq[j * TT + t] - 2.0f * cross + asqi) * is2;
                if (j == i) { g_self[i] = d; d = -10000.0f; }
                g_dist[(size_t)i * NNEG + j] = d;
            }
        }
    }
}

// ============ Kernel 6: per-row top-5 + self -> brownian term ============
__global__ void __launch_bounds__(256) topk_kernel()
{
    int i = blockIdx.x;
    __shared__ float cand[256 * 5];
    float t5[5] = {-1e30f, -1e30f, -1e30f, -1e30f, -1e30f};
    const float* row = &g_dist[(size_t)i * NNEG];
    for (int j = threadIdx.x; j < NNEG; j += 256) {
        float v = row[j];
        if (v > t5[4]) {
            int k = 4;
            while (k > 0 && v > t5[k - 1]) { t5[k] = t5[k - 1]; k--; }
            t5[k] = v;
        }
    }
    #pragma unroll
    for (int k = 0; k < 5; k++) cand[threadIdx.x * 5 + k] = t5[k];
    __syncthreads();
    if (threadIdx.x == 0) {
        float best[5] = {-1e30f, -1e30f, -1e30f, -1e30f, -1e30f};
        for (int m = 0; m < 256 * 5; m++) {
            float v = cand[m];
            if (v > best[4]) {
                int k = 4;
                while (k > 0 && v > best[k - 1]) { best[k] = best[k - 1]; k--; }
                best[k] = v;
            }
        }
        float deno = expf(g_self[i]);
        #pragma unroll
        for (int k = 0; k < 5; k++) deno += expf(best[k]);
        g_brown[i] = g_numer[i] / deno;
    }
}

// ============ Kernel 7: head-tail softplus term ============
__global__ void __launch_bounds__(256) headtail_kernel()
{
    int warp = threadIdx.x >> 5;
    int lane = threadIdx.x & 31;
    int i = blockIdx.x * 8 + warp;
    size_t r0 = (size_t)(i * TT + 0) * PROJD;
    size_t r1 = (size_t)(i * TT + (TT - 1)) * PROJD;
    float s = 0.0f;
    #pragma unroll
    for (int h = 0; h < 2; h++) {
        int c = h * 128 + lane * 4;
        float a[4], b4[4];
        ld_rec4(g_neg_h, g_neg_l, r0 + c, a);
        ld_rec4(g_neg_h, g_neg_l, r1 + c, b4);
        s += a[0]*b4[0] + a[1]*b4[1] + a[2]*b4[2] + a[3]*b4[3];
    }
    s = warp_sum(s);
    if (lane == 0) {
        float z = 0.3f - s;
        g_ht[i] = log1pf(expf(z));
    }
}

// ============ Kernel 8: deterministic final reduction ============
__global__ void __launch_bounds__(256) final_kernel(float* __restrict__ out)
{
    __shared__ float sb[256], sh[256];
    int tid = threadIdx.x;
    float b = 0.0f, h = 0.0f;
    for (int i = tid; i < NI; i += 256) { b += g_brown[i]; h += g_ht[i]; }
    sb[tid] = b; sh[tid] = h;
    __syncthreads();
    for (int s = 128; s > 0; s >>= 1) {
        if (tid < s) { sb[tid] += sb[tid + s]; sh[tid] += sh[tid + s]; }
        __syncthreads();
    }
    if (tid == 0) {
        out[0] = sb[0] / (float)NI;
        out[1] = sh[0] / (float)NI;
    }
}

// ==================== launch ====================
extern "C" void kernel_launch(void* const* d_in, const int* in_sizes, int n_in,
                              void* d_out, int out_size)
{
    const float* fe     = (const float*)d_in[0];
    const float* ofe    = (const float*)d_in[1];
    const float* W      = (const float*)d_in[2];
    const float* bias   = (const float*)d_in[3];
    const int*   bridge = (const int*)d_in[4];
    float* out = (float*)d_out;

    cudaFuncSetAttribute(proj_mma_kernel, cudaFuncAttributeMaxDynamicSharedMemorySize, PROJ_SMEM);
    cudaFuncSetAttribute(dist_mma_kernel, cudaFuncAttributeMaxDynamicSharedMemorySize, DIST_SMEM);

    convert_w_kernel<<<HIDD, PROJD>>>(W);
    proj_mma_kernel<<<400, 256, PROJ_SMEM>>>(fe, ofe, bias);

    bridge_prep_kernel<<<NI / 8, 256>>>(bridge);
    bucket_kernel<<<1, 256>>>();
    dist_mma_kernel<<<dim3(NNEG / 64, TT), 256, DIST_SMEM>>>();
    topk_kernel<<<NI, 256>>>();
    headtail_kernel<<<NI / 8, 256>>>();
    final_kernel<<<1, 256>>>(out);
}

// round 6
// speedup vs baseline: 1.9206x; 1.2313x over previous
#include <cstdint>
#include <stdint.h>
#include <cuda_runtime.h>
#include <cuda_bf16.h>
#include <mma.h>
#include <math.h>

using namespace nvcuda;

#define BSZ   16
#define TT    16
#define QQ    100
#define HIDD  256
#define PROJD 256
#define NI    1600    // BS*Q
#define MROWS 25600   // BS*T*Q
#define NNEG  3200

// -------- scratch (device globals; no allocation allowed) --------
__device__ __nv_bfloat16 g_neg_h[NNEG * TT * PROJD];   // 26.2 MB  [j, t, c] hi
__device__ __nv_bfloat16 g_neg_l[NNEG * TT * PROJD];   // 26.2 MB  lo
__device__ float g_nsq[NNEG * TT];                     // sum(neg^2) per (j,t)
__device__ __nv_bfloat16 g_a_h[NI * PROJD];
__device__ __nv_bfloat16 g_a_l[NI * PROJD];
__device__ float g_asq[NI];
__device__ float g_numer[NI];
__device__ float g_inv2s[NI];
__device__ int   g_bp[NI];
__device__ float g_dist[NI * NNEG];              // 20.5 MB
__device__ float g_self[NI];
__device__ float g_brown[NI];
__device__ float g_ht[NI];
__device__ __nv_bfloat16 g_wt_hi[PROJD * HIDD];  // W^T split-hi  [n][k]
__device__ __nv_bfloat16 g_wt_lo[PROJD * HIDD];  // W^T split-lo  [n][k]

__device__ __forceinline__ float warp_sum(float v) {
    #pragma unroll
    for (int o = 16; o > 0; o >>= 1) v += __shfl_xor_sync(0xffffffffu, v, o);
    return v;
}

// reconstruct 4 floats from hi/lo bf16 arrays at index idx (8-byte aligned)
__device__ __forceinline__ void ld_rec4(const __nv_bfloat16* __restrict__ h,
                                        const __nv_bfloat16* __restrict__ l,
                                        size_t idx, float* out) {
    __nv_bfloat162 h0 = *(const __nv_bfloat162*)&h[idx];
    __nv_bfloat162 h1 = *(const __nv_bfloat162*)&h[idx + 2];
    __nv_bfloat162 l0 = *(const __nv_bfloat162*)&l[idx];
    __nv_bfloat162 l1 = *(const __nv_bfloat162*)&l[idx + 2];
    out[0] = __bfloat162float(h0.x) + __bfloat162float(l0.x);
    out[1] = __bfloat162float(h0.y) + __bfloat162float(l0.y);
    out[2] = __bfloat162float(h1.x) + __bfloat162float(l1.x);
    out[3] = __bfloat162float(h1.y) + __bfloat162float(l1.y);
}

// sorted-desc top-5 insert
__device__ __forceinline__ void ins5(float* t5, float v) {
    if (v > t5[4]) {
        if (v > t5[0])      { t5[4]=t5[3]; t5[3]=t5[2]; t5[2]=t5[1]; t5[1]=t5[0]; t5[0]=v; }
        else if (v > t5[1]) { t5[4]=t5[3]; t5[3]=t5[2]; t5[2]=t5[1]; t5[1]=v; }
        else if (v > t5[2]) { t5[4]=t5[3]; t5[3]=t5[2]; t5[2]=v; }
        else if (v > t5[3]) { t5[4]=t5[3]; t5[3]=v; }
        else                { t5[4]=v; }
    }
}

// ============ Kernel 0: W -> W^T split into bf16 hi/lo ============
__global__ void __launch_bounds__(256) convert_w_kernel(const float* __restrict__ W)
{
    int k = blockIdx.x;      // 0..255 (HID)
    int n = threadIdx.x;     // 0..255 (PROJ)
    float v = W[k * PROJD + n];
    __nv_bfloat16 h = __float2bfloat16(v);
    g_wt_hi[n * HIDD + k] = h;
    g_wt_lo[n * HIDD + k] = __float2bfloat16(v - __bfloat162float(h));
}

// ============ Kernel 1: wmma bf16-split projection (64M x 256N per CTA) ============
// 2 CTAs/SM for load<->MMA overlap. 8 warps = 2(M) x 4(N), warp tile 32x64.
#define KC   64
#define LDA  72
#define LDB  72
#define STG_LD 260

#define OFF_BIAS  0
#define OFF_U     1024
#define OFF_A_HI  (OFF_U)
#define OFF_A_LO  (OFF_A_HI + 64 * LDA * 2)
#define OFF_B_HI  (OFF_A_LO + 64 * LDA * 2)
#define OFF_B_LO  (OFF_B_HI + 256 * LDB * 2)
#define TILES_END (OFF_B_LO + 256 * LDB * 2)     // 1024 + 18432 + 73728 = 93184
#define STG_END   (OFF_U + 64 * STG_LD * 4)      // 1024 + 66560 (overlay < TILES_END)
#define PROJ_SMEM (STG_END > TILES_END ? STG_END : TILES_END)

__global__ void __launch_bounds__(256, 2) proj_mma_kernel(
    const float* __restrict__ fe, const float* __restrict__ ofe,
    const float* __restrict__ bias)
{
    extern __shared__ char smem_raw[];
    float* bias_s = (float*)(smem_raw + OFF_BIAS);
    __nv_bfloat16* Ah = (__nv_bfloat16*)(smem_raw + OFF_A_HI);
    __nv_bfloat16* Al = (__nv_bfloat16*)(smem_raw + OFF_A_LO);
    __nv_bfloat16* Bh = (__nv_bfloat16*)(smem_raw + OFF_B_HI);
    __nv_bfloat16* Bl = (__nv_bfloat16*)(smem_raw + OFF_B_LO);
    float* stage = (float*)(smem_raw + OFF_U);

    int tid  = threadIdx.x;
    int wid  = tid >> 5;
    int lane = tid & 31;

    int b = blockIdx.x;                 // 0..799
    const float* A = (b < 400) ? fe : ofe;
    int base = (b < 400) ? 0 : NI;
    int m0   = (b % 400) * 64;

    bias_s[tid] = bias[tid];

    int wm = wid >> 2;                  // 0..1
    int wn = wid & 3;                   // 0..3

    wmma::fragment<wmma::accumulator, 16, 16, 16, float> acc[2][4];
    #pragma unroll
    for (int mt = 0; mt < 2; mt++)
        #pragma unroll
        for (int nt = 0; nt < 4; nt++)
            wmma::fill_fragment(acc[mt][nt], 0.0f);

    for (int c = 0; c < 4; c++) {
        int k0 = c * KC;
        __syncthreads();
        // ---- load & split A chunk: 64 rows x 64 fp32 ----
        #pragma unroll
        for (int it = 0; it < 4; it++) {
            int flat = it * 256 + tid;     // 0..1023
            int row  = flat >> 4;          // 0..63
            int j    = flat & 15;
            float4 v = *(const float4*)&A[(size_t)(m0 + row) * HIDD + k0 + j * 4];
            __nv_bfloat16 h0 = __float2bfloat16(v.x);
            __nv_bfloat16 h1 = __float2bfloat16(v.y);
            __nv_bfloat16 h2 = __float2bfloat16(v.z);
            __nv_bfloat16 h3 = __float2bfloat16(v.w);
            __nv_bfloat16 l0 = __float2bfloat16(v.x - __bfloat162float(h0));
            __nv_bfloat16 l1 = __float2bfloat16(v.y - __bfloat162float(h1));
            __nv_bfloat16 l2 = __float2bfloat16(v.z - __bfloat162float(h2));
            __nv_bfloat16 l3 = __float2bfloat16(v.w - __bfloat162float(h3));
            int o = row * LDA + j * 4;
            *(__nv_bfloat162*)&Ah[o]     = __nv_bfloat162{h0, h1};
            *(__nv_bfloat162*)&Ah[o + 2] = __nv_bfloat162{h2, h3};
            *(__nv_bfloat162*)&Al[o]     = __nv_bfloat162{l0, l1};
            *(__nv_bfloat162*)&Al[o + 2] = __nv_bfloat162{l2, l3};
        }
        // ---- load B chunk (pre-split): 256 n x 64 k ----
        #pragma unroll
        for (int it = 0; it < 8; it++) {
            int flat = it * 256 + tid;
            int n = flat >> 3;
            int u = flat & 7;
            uint4 vh = *(const uint4*)&g_wt_hi[(size_t)n * HIDD + k0 + u * 8];
            uint4 vl = *(const uint4*)&g_wt_lo[(size_t)n * HIDD + k0 + u * 8];
            *(uint4*)&Bh[n * LDB + u * 8] = vh;
            *(uint4*)&Bl[n * LDB + u * 8] = vl;
        }
        __syncthreads();

        #pragma unroll
        for (int kt = 0; kt < KC / 16; kt++) {
            wmma::fragment<wmma::matrix_a, 16, 16, 16, __nv_bfloat16, wmma::row_major> ah[2], al[2];
            #pragma unroll
            for (int mt = 0; mt < 2; mt++) {
                int row0 = wm * 32 + mt * 16;
                wmma::load_matrix_sync(ah[mt], Ah + row0 * LDA + kt * 16, LDA);
                wmma::load_matrix_sync(al[mt], Al + row0 * LDA + kt * 16, LDA);
            }
            #pragma unroll
            for (int nt = 0; nt < 4; nt++) {
                int n0 = wn * 64 + nt * 16;
                wmma::fragment<wmma::matrix_b, 16, 16, 16, __nv_bfloat16, wmma::col_major> bh, bl;
                wmma::load_matrix_sync(bh, Bh + n0 * LDB + kt * 16, LDB);
                wmma::load_matrix_sync(bl, Bl + n0 * LDB + kt * 16, LDB);
                #pragma unroll
                for (int mt = 0; mt < 2; mt++) {
                    wmma::mma_sync(acc[mt][nt], ah[mt], bh, acc[mt][nt]);
                    wmma::mma_sync(acc[mt][nt], al[mt], bh, acc[mt][nt]);
                    wmma::mma_sync(acc[mt][nt], ah[mt], bl, acc[mt][nt]);
                }
            }
        }
    }

    __syncthreads();
    #pragma unroll
    for (int mt = 0; mt < 2; mt++) {
        int row0 = wm * 32 + mt * 16;
        #pragma unroll
        for (int nt = 0; nt < 4; nt++) {
            int n0 = wn * 64 + nt * 16;
            wmma::store_matrix_sync(stage + row0 * STG_LD + n0, acc[mt][nt],
                                    STG_LD, wmma::mem_row_major);
        }
    }
    __syncthreads();

    // ---- epilogue: bias + L2-normalize + transposed bf16 hi/lo write ----
    // warp w handles rows [w*8, w*8+8)
    for (int rr = 0; rr < 8; rr++) {
        int r = wid * 8 + rr;
        float v[8];
        float ss = 0.0f;
        #pragma unroll
        for (int u = 0; u < 8; u++) {
            int cidx = lane + 32 * u;
            float x = stage[r * STG_LD + cidx] + bias_s[cidx];
            v[u] = x;
            ss += x * x;
        }
        ss = warp_sum(ss);
        float inv = rsqrtf(ss);
        int m = m0 + r;
        int q = m % QQ;
        int t = (m / QQ) % TT;
        int bs = m / (QQ * TT);
        int orow = (base + bs * QQ + q) * TT + t;
        #pragma unroll
        for (int u = 0; u < 8; u++) {
            float x = v[u] * inv;
            __nv_bfloat16 h = __float2bfloat16(x);
            size_t o = (size_t)orow * PROJD + lane + 32 * u;
            g_neg_h[o] = h;
            g_neg_l[o] = __float2bfloat16(x - __bfloat162float(h));
        }
        if (lane == 0) g_nsq[orow] = ss * inv * inv;
    }
}

// ============ Kernel 2: bridge prep + fused head-tail ============
__global__ void __launch_bounds__(256) bridge_prep_kernel(const int* __restrict__ bridge)
{
    int warp = threadIdx.x >> 5;
    int lane = threadIdx.x & 31;
    int i = blockIdx.x * 8 + warp;        // 0..1599
    int bh = bridge[i * 3 + 0];           // == 0 by construction
    int bp = bridge[i * 3 + 1];
    int bt = bridge[i * 3 + 2];           // == TT-1 by construction
    float bhf = (float)bh, bpf = (float)bp, btf = (float)bt;
    float alpha = (bpf - bhf) / (btf - bhf);
    float sigma = alpha * (btf - bpf);
    float inv2s = 1.0f / (2.0f * sigma * sigma);

    size_t r0 = (size_t)(i * TT + bh) * PROJD;
    size_t r1 = (size_t)(i * TT + bp) * PROJD;
    size_t r2 = (size_t)(i * TT + bt) * PROJD;
    float oma = 1.0f - alpha;
    float xs = 0.0f, as = 0.0f, ht = 0.0f;
    #pragma unroll
    for (int h = 0; h < 2; h++) {
        int c = h * 128 + lane * 4;
        float g0[4], g1[4], g2[4];
        ld_rec4(g_neg_h, g_neg_l, r0 + c, g0);
        ld_rec4(g_neg_h, g_neg_l, r1 + c, g1);
        ld_rec4(g_neg_h, g_neg_l, r2 + c, g2);
        #pragma unroll
        for (int e = 0; e < 4; e++) {
            float aa = oma * g0[e] + alpha * g2[e];
            float x  = g1[e] - oma * g0[e] - alpha * g2[e];
            xs += x * x;
            as += aa * aa;
            ht += g0[e] * g2[e];          // head(t=0) . tail(t=15): bh==0, bt==15
            __nv_bfloat16 ahv = __float2bfloat16(aa);
            size_t o = (size_t)i * PROJD + c + e;
            g_a_h[o] = ahv;
            g_a_l[o] = __float2bfloat16(aa - __bfloat162float(ahv));
        }
    }
    xs = warp_sum(xs);
    as = warp_sum(as);
    ht = warp_sum(ht);
    if (lane == 0) {
        g_bp[i]    = bp;
        g_inv2s[i] = inv2s;
        g_asq[i]   = as;
        g_numer[i] = expf(-xs * inv2s);
        float z = 0.3f - ht;
        g_ht[i] = log1pf(expf(z));
    }
}

// ============ Kernel 3: bucketed dist GEMM (wmma, inline bucketing) ============
#define DLD   264
#define DSTG  72
#define D_OFF_AH  0
#define D_OFF_AL  (D_OFF_AH + 32 * DLD * 2)
#define D_OFF_BH  (D_OFF_AL + 32 * DLD * 2)
#define D_OFF_BL  (D_OFF_BH + 64 * DLD * 2)
#define D_OFF_STG (D_OFF_BL + 64 * DLD * 2)
#define D_OFF_FUL (D_OFF_STG + 32 * DSTG * 4)
#define D_OFF_CNT (D_OFF_FUL + NI * 4)
#define DIST_SMEM (D_OFF_CNT + 16)

__global__ void __launch_bounds__(256, 1) dist_mma_kernel()
{
    extern __shared__ char smem_raw[];
    __nv_bfloat16* Ah = (__nv_bfloat16*)(smem_raw + D_OFF_AH);
    __nv_bfloat16* Al = (__nv_bfloat16*)(smem_raw + D_OFF_AL);
    __nv_bfloat16* Bh = (__nv_bfloat16*)(smem_raw + D_OFF_BH);
    __nv_bfloat16* Bl = (__nv_bfloat16*)(smem_raw + D_OFF_BL);
    float* stage = (float*)(smem_raw + D_OFF_STG);
    int* sfull = (int*)(smem_raw + D_OFF_FUL);
    int* scnt  = (int*)(smem_raw + D_OFF_CNT);

    int t = blockIdx.y;
    int j0 = blockIdx.x * 64;
    int tid = threadIdx.x;
    int wid = tid >> 5;
    int wm = wid >> 2;    // 0..1  (i)
    int wn = wid & 3;     // 0..3  (j)

    // ---- build bucket list for this t (value-deterministic; order free) ----
    if (tid == 0) scnt[0] = 0;
    __syncthreads();
    for (int i = tid; i < NI; i += 256) {
        if (g_bp[i] == t) {
            int pos = atomicAdd(scnt, 1);
            sfull[pos] = i;
        }
    }
    __syncthreads();
    int cnt = scnt[0];
    if (cnt == 0) return;

    // ---- load B tiles once: 64 j-rows x 256 k, hi/lo ----
    #pragma unroll
    for (int it = 0; it < 8; it++) {
        int flat = it * 256 + tid;
        int jr = flat >> 5;
        int k8 = flat & 31;
        size_t src = (size_t)((j0 + jr) * TT + t) * PROJD + k8 * 8;
        *(uint4*)&Bh[jr * DLD + k8 * 8] = *(const uint4*)&g_neg_h[src];
        *(uint4*)&Bl[jr * DLD + k8 * 8] = *(const uint4*)&g_neg_l[src];
    }

    for (int ic = 0; ic < cnt; ic += 32) {
        int cc = min(32, cnt - ic);
        __syncthreads();

        // ---- load A tiles: 32 rows x 256 k (gather) ----
        #pragma unroll
        for (int it = 0; it < 4; it++) {
            int flat = it * 256 + tid;
            int r  = flat >> 5;
            int k8 = flat & 31;
            int row_i = sfull[ic + ((r < cc) ? r : 0)];
            size_t src = (size_t)row_i * PROJD + k8 * 8;
            *(uint4*)&Ah[r * DLD + k8 * 8] = *(const uint4*)&g_a_h[src];
            *(uint4*)&Al[r * DLD + k8 * 8] = *(const uint4*)&g_a_l[src];
        }
        __syncthreads();

        wmma::fragment<wmma::accumulator, 16, 16, 16, float> acc;
        wmma::fill_fragment(acc, 0.0f);
        #pragma unroll
        for (int kt = 0; kt < 16; kt++) {
            wmma::fragment<wmma::matrix_a, 16, 16, 16, __nv_bfloat16, wmma::row_major> ah, al;
            wmma::fragment<wmma::matrix_b, 16, 16, 16, __nv_bfloat16, wmma::col_major> bh, bl;
            wmma::load_matrix_sync(ah, Ah + (wm * 16) * DLD + kt * 16, DLD);
            wmma::load_matrix_sync(al, Al + (wm * 16) * DLD + kt * 16, DLD);
            wmma::load_matrix_sync(bh, Bh + (wn * 16) * DLD + kt * 16, DLD);
            wmma::load_matrix_sync(bl, Bl + (wn * 16) * DLD + kt * 16, DLD);
            wmma::mma_sync(acc, ah, bh, acc);
            wmma::mma_sync(acc, al, bh, acc);
            wmma::mma_sync(acc, ah, bl, acc);
        }
        wmma::store_matrix_sync(stage + (wm * 16) * DSTG + wn * 16, acc,
                                DSTG, wmma::mem_row_major);
        __syncthreads();

        int r  = tid >> 3;
        int c0 = (tid & 7) * 8;
        if (r < cc) {
            int i = sfull[ic + r];
            float asqi = g_asq[i];
            float is2  = g_inv2s[i];
            #pragma unroll
            for (int u = 0; u < 8; u++) {
                int j = j0 + c0 + u;
                float cross = stage[r * DSTG + c0 + u];
                float d = -(g_nsq[j * TT + t] - 2.0f * cross + asqi) * is2;
                if (j == i) { g_self[i] = d; d = -10000.0f; }
                g_dist[(size_t)i * NNEG + j] = d;
            }
        }
    }
}

// ============ Kernel 4: warp-per-row top-5 + brownian term ============
__global__ void __launch_bounds__(256) topk_kernel()
{
    int wid  = threadIdx.x >> 5;
    int lane = threadIdx.x & 31;
    int i = blockIdx.x * 8 + wid;         // 0..1599
    const float* row = &g_dist[(size_t)i * NNEG];

    float t5[5] = {-1e30f, -1e30f, -1e30f, -1e30f, -1e30f};
    #pragma unroll 4
    for (int k = 0; k < NNEG / 128; k++) {          // 25 iters
        float4 v = *(const float4*)&row[k * 128 + lane * 4];
        ins5(t5, v.x); ins5(t5, v.y); ins5(t5, v.z); ins5(t5, v.w);
    }
    // cross-lane merge of sorted-5 lists
    #pragma unroll
    for (int off = 16; off > 0; off >>= 1) {
        float b0 = __shfl_xor_sync(0xffffffffu, t5[0], off);
        float b1 = __shfl_xor_sync(0xffffffffu, t5[1], off);
        float b2 = __shfl_xor_sync(0xffffffffu, t5[2], off);
        float b3 = __shfl_xor_sync(0xffffffffu, t5[3], off);
        float b4 = __shfl_xor_sync(0xffffffffu, t5[4], off);
        ins5(t5, b0); ins5(t5, b1); ins5(t5, b2); ins5(t5, b3); ins5(t5, b4);
    }
    if (lane == 0) {
        float deno = expf(g_self[i]);
        #pragma unroll
        for (int k = 0; k < 5; k++) deno += expf(t5[k]);
        g_brown[i] = g_numer[i] / deno;
    }
}

// ============ Kernel 5: deterministic final reduction ============
__global__ void __launch_bounds__(256) final_kernel(float* __restrict__ out)
{
    __shared__ float sb[256], sh[256];
    int tid = threadIdx.x;
    float b = 0.0f, h = 0.0f;
    for (int i = tid; i < NI; i += 256) { b += g_brown[i]; h += g_ht[i]; }
    sb[tid] = b; sh[tid] = h;
    __syncthreads();
    for (int s = 128; s > 0; s >>= 1) {
        if (tid < s) { sb[tid] += sb[tid + s]; sh[tid] += sh[tid + s]; }
        __syncthreads();
    }
    if (tid == 0) {
        out[0] = sb[0] / (float)NI;
        out[1] = sh[0] / (float)NI;
    }
}

// ==================== launch ====================
extern "C" void kernel_launch(void* const* d_in, const int* in_sizes, int n_in,
                              void* d_out, int out_size)
{
    const float* fe     = (const float*)d_in[0];
    const float* ofe    = (const float*)d_in[1];
    const float* W      = (const float*)d_in[2];
    const float* bias   = (const float*)d_in[3];
    const int*   bridge = (const int*)d_in[4];
    float* out = (float*)d_out;

    cudaFuncSetAttribute(proj_mma_kernel, cudaFuncAttributeMaxDynamicSharedMemorySize, PROJ_SMEM);
    cudaFuncSetAttribute(dist_mma_kernel, cudaFuncAttributeMaxDynamicSharedMemorySize, DIST_SMEM);

    convert_w_kernel<<<HIDD, PROJD>>>(W);
    proj_mma_kernel<<<800, 256, PROJ_SMEM>>>(fe, ofe, bias);

    bridge_prep_kernel<<<NI / 8, 256>>>(bridge);
    dist_mma_kernel<<<dim3(NNEG / 64, TT), 256, DIST_SMEM>>>();
    topk_kernel<<<NI / 8, 256>>>();
    final_kernel<<<1, 256>>>(out);
}

// round 7
// speedup vs baseline: 2.1413x; 1.1149x over previous
#include <cstdint>
#include <stdint.h>
#include <cuda_runtime.h>
#include <cuda_bf16.h>
#include <mma.h>
#include <math.h>

using namespace nvcuda;

#define BSZ   16
#define TT    16
#define QQ    100
#define HIDD  256
#define PROJD 256
#define NI    1600    // BS*Q
#define MROWS 25600   // BS*T*Q
#define NNEG  3200
#define MAXC  (NI / 64 + TT)   // 41 chunk slots upper bound

// -------- scratch (device globals; no allocation allowed) --------
__device__ __nv_bfloat16 g_neg_h[NNEG * TT * PROJD];   // 26.2 MB  [j, t, c] hi
__device__ __nv_bfloat16 g_neg_l[NNEG * TT * PROJD];   // 26.2 MB  lo
__device__ float g_nsq[NNEG * TT];                     // sum(neg^2) per (j,t)
__device__ __nv_bfloat16 g_a_h[NI * PROJD];
__device__ __nv_bfloat16 g_a_l[NI * PROJD];
__device__ float g_asq[NI];
__device__ float g_numer[NI];
__device__ float g_inv2s[NI];
__device__ float g_dist[NI * NNEG];              // 20.5 MB
__device__ float g_self[NI];
__device__ float g_brown[NI];
__device__ float g_ht[NI];
__device__ __nv_bfloat16 g_wt_hi[PROJD * HIDD];  // W^T split-hi  [n][k]
__device__ __nv_bfloat16 g_wt_lo[PROJD * HIDD];  // W^T split-lo  [n][k]
__device__ int g_bucket_cnt[TT];
__device__ int g_bitems[TT * NI];                // bucket item lists
__device__ int g_chunk_t[MAXC];
__device__ int g_chunk_off[MAXC];
__device__ int g_nchunks;

__device__ __forceinline__ float warp_sum(float v) {
    #pragma unroll
    for (int o = 16; o > 0; o >>= 1) v += __shfl_xor_sync(0xffffffffu, v, o);
    return v;
}

// reconstruct 4 floats from hi/lo bf16 arrays at index idx (8-byte aligned)
__device__ __forceinline__ void ld_rec4(const __nv_bfloat16* __restrict__ h,
                                        const __nv_bfloat16* __restrict__ l,
                                        size_t idx, float* out) {
    __nv_bfloat162 h0 = *(const __nv_bfloat162*)&h[idx];
    __nv_bfloat162 h1 = *(const __nv_bfloat162*)&h[idx + 2];
    __nv_bfloat162 l0 = *(const __nv_bfloat162*)&l[idx];
    __nv_bfloat162 l1 = *(const __nv_bfloat162*)&l[idx + 2];
    out[0] = __bfloat162float(h0.x) + __bfloat162float(l0.x);
    out[1] = __bfloat162float(h0.y) + __bfloat162float(l0.y);
    out[2] = __bfloat162float(h1.x) + __bfloat162float(l1.x);
    out[3] = __bfloat162float(h1.y) + __bfloat162float(l1.y);
}

// sorted-desc top-5 insert
__device__ __forceinline__ void ins5(float* t5, float v) {
    if (v > t5[4]) {
        if (v > t5[0])      { t5[4]=t5[3]; t5[3]=t5[2]; t5[2]=t5[1]; t5[1]=t5[0]; t5[0]=v; }
        else if (v > t5[1]) { t5[4]=t5[3]; t5[3]=t5[2]; t5[2]=t5[1]; t5[1]=v; }
        else if (v > t5[2]) { t5[4]=t5[3]; t5[3]=t5[2]; t5[2]=v; }
        else if (v > t5[3]) { t5[4]=t5[3]; t5[3]=v; }
        else                { t5[4]=v; }
    }
}

// ============ Kernel 0: W -> W^T split into bf16 hi/lo (+ zero bucket counters) ============
__global__ void __launch_bounds__(256) convert_w_kernel(const float* __restrict__ W)
{
    if (blockIdx.x == 0 && threadIdx.x < TT) g_bucket_cnt[threadIdx.x] = 0;
    int k = blockIdx.x;      // 0..255 (HID)
    int n = threadIdx.x;     // 0..255 (PROJ)
    float v = W[k * PROJD + n];
    __nv_bfloat16 h = __float2bfloat16(v);
    g_wt_hi[n * HIDD + k] = h;
    g_wt_lo[n * HIDD + k] = __float2bfloat16(v - __bfloat162float(h));
}

// ============ Kernel 1: wmma bf16-split projection (64M x 256N per CTA) ============
#define KC   64
#define LDA  72
#define LDB  72
#define STG_LD 260

#define OFF_BIAS  0
#define OFF_U     1024
#define OFF_A_HI  (OFF_U)
#define OFF_A_LO  (OFF_A_HI + 64 * LDA * 2)
#define OFF_B_HI  (OFF_A_LO + 64 * LDA * 2)
#define OFF_B_LO  (OFF_B_HI + 256 * LDB * 2)
#define TILES_END (OFF_B_LO + 256 * LDB * 2)
#define STG_END   (OFF_U + 64 * STG_LD * 4)
#define PROJ_SMEM (STG_END > TILES_END ? STG_END : TILES_END)

__global__ void __launch_bounds__(256, 2) proj_mma_kernel(
    const float* __restrict__ fe, const float* __restrict__ ofe,
    const float* __restrict__ bias)
{
    extern __shared__ char smem_raw[];
    float* bias_s = (float*)(smem_raw + OFF_BIAS);
    __nv_bfloat16* Ah = (__nv_bfloat16*)(smem_raw + OFF_A_HI);
    __nv_bfloat16* Al = (__nv_bfloat16*)(smem_raw + OFF_A_LO);
    __nv_bfloat16* Bh = (__nv_bfloat16*)(smem_raw + OFF_B_HI);
    __nv_bfloat16* Bl = (__nv_bfloat16*)(smem_raw + OFF_B_LO);
    float* stage = (float*)(smem_raw + OFF_U);

    int tid  = threadIdx.x;
    int wid  = tid >> 5;
    int lane = tid & 31;

    int b = blockIdx.x;
    const float* A = (b < 400) ? fe : ofe;
    int base = (b < 400) ? 0 : NI;
    int m0   = (b % 400) * 64;

    bias_s[tid] = bias[tid];

    int wm = wid >> 2;
    int wn = wid & 3;

    wmma::fragment<wmma::accumulator, 16, 16, 16, float> acc[2][4];
    #pragma unroll
    for (int mt = 0; mt < 2; mt++)
        #pragma unroll
        for (int nt = 0; nt < 4; nt++)
            wmma::fill_fragment(acc[mt][nt], 0.0f);

    for (int c = 0; c < 4; c++) {
        int k0 = c * KC;
        __syncthreads();
        #pragma unroll
        for (int it = 0; it < 4; it++) {
            int flat = it * 256 + tid;
            int row  = flat >> 4;
            int j    = flat & 15;
            float4 v = *(const float4*)&A[(size_t)(m0 + row) * HIDD + k0 + j * 4];
            __nv_bfloat16 h0 = __float2bfloat16(v.x);
            __nv_bfloat16 h1 = __float2bfloat16(v.y);
            __nv_bfloat16 h2 = __float2bfloat16(v.z);
            __nv_bfloat16 h3 = __float2bfloat16(v.w);
            __nv_bfloat16 l0 = __float2bfloat16(v.x - __bfloat162float(h0));
            __nv_bfloat16 l1 = __float2bfloat16(v.y - __bfloat162float(h1));
            __nv_bfloat16 l2 = __float2bfloat16(v.z - __bfloat162float(h2));
            __nv_bfloat16 l3 = __float2bfloat16(v.w - __bfloat162float(h3));
            int o = row * LDA + j * 4;
            *(__nv_bfloat162*)&Ah[o]     = __nv_bfloat162{h0, h1};
            *(__nv_bfloat162*)&Ah[o + 2] = __nv_bfloat162{h2, h3};
            *(__nv_bfloat162*)&Al[o]     = __nv_bfloat162{l0, l1};
            *(__nv_bfloat162*)&Al[o + 2] = __nv_bfloat162{l2, l3};
        }
        #pragma unroll
        for (int it = 0; it < 8; it++) {
            int flat = it * 256 + tid;
            int n = flat >> 3;
            int u = flat & 7;
            uint4 vh = *(const uint4*)&g_wt_hi[(size_t)n * HIDD + k0 + u * 8];
            uint4 vl = *(const uint4*)&g_wt_lo[(size_t)n * HIDD + k0 + u * 8];
            *(uint4*)&Bh[n * LDB + u * 8] = vh;
            *(uint4*)&Bl[n * LDB + u * 8] = vl;
        }
        __syncthreads();

        #pragma unroll
        for (int kt = 0; kt < KC / 16; kt++) {
            wmma::fragment<wmma::matrix_a, 16, 16, 16, __nv_bfloat16, wmma::row_major> ah[2], al[2];
            #pragma unroll
            for (int mt = 0; mt < 2; mt++) {
                int row0 = wm * 32 + mt * 16;
                wmma::load_matrix_sync(ah[mt], Ah + row0 * LDA + kt * 16, LDA);
                wmma::load_matrix_sync(al[mt], Al + row0 * LDA + kt * 16, LDA);
            }
            #pragma unroll
            for (int nt = 0; nt < 4; nt++) {
                int n0 = wn * 64 + nt * 16;
                wmma::fragment<wmma::matrix_b, 16, 16, 16, __nv_bfloat16, wmma::col_major> bh, bl;
                wmma::load_matrix_sync(bh, Bh + n0 * LDB + kt * 16, LDB);
                wmma::load_matrix_sync(bl, Bl + n0 * LDB + kt * 16, LDB);
                #pragma unroll
                for (int mt = 0; mt < 2; mt++) {
                    wmma::mma_sync(acc[mt][nt], ah[mt], bh, acc[mt][nt]);
                    wmma::mma_sync(acc[mt][nt], al[mt], bh, acc[mt][nt]);
                    wmma::mma_sync(acc[mt][nt], ah[mt], bl, acc[mt][nt]);
                }
            }
        }
    }

    __syncthreads();
    #pragma unroll
    for (int mt = 0; mt < 2; mt++) {
        int row0 = wm * 32 + mt * 16;
        #pragma unroll
        for (int nt = 0; nt < 4; nt++) {
            int n0 = wn * 64 + nt * 16;
            wmma::store_matrix_sync(stage + row0 * STG_LD + n0, acc[mt][nt],
                                    STG_LD, wmma::mem_row_major);
        }
    }
    __syncthreads();

    for (int rr = 0; rr < 8; rr++) {
        int r = wid * 8 + rr;
        float v[8];
        float ss = 0.0f;
        #pragma unroll
        for (int u = 0; u < 8; u++) {
            int cidx = lane + 32 * u;
            float x = stage[r * STG_LD + cidx] + bias_s[cidx];
            v[u] = x;
            ss += x * x;
        }
        ss = warp_sum(ss);
        float inv = rsqrtf(ss);
        int m = m0 + r;
        int q = m % QQ;
        int t = (m / QQ) % TT;
        int bs = m / (QQ * TT);
        int orow = (base + bs * QQ + q) * TT + t;
        #pragma unroll
        for (int u = 0; u < 8; u++) {
            float x = v[u] * inv;
            __nv_bfloat16 h = __float2bfloat16(x);
            size_t o = (size_t)orow * PROJD + lane + 32 * u;
            g_neg_h[o] = h;
            g_neg_l[o] = __float2bfloat16(x - __bfloat162float(h));
        }
        if (lane == 0) g_nsq[orow] = ss * inv * inv;
    }
}

// ============ Kernel 2: bridge prep + fused head-tail + bucket push ============
__global__ void __launch_bounds__(256) bridge_prep_kernel(const int* __restrict__ bridge)
{
    int warp = threadIdx.x >> 5;
    int lane = threadIdx.x & 31;
    int i = blockIdx.x * 8 + warp;        // 0..1599
    int bh = bridge[i * 3 + 0];
    int bp = bridge[i * 3 + 1];
    int bt = bridge[i * 3 + 2];
    float bhf = (float)bh, bpf = (float)bp, btf = (float)bt;
    float alpha = (bpf - bhf) / (btf - bhf);
    float sigma = alpha * (btf - bpf);
    float inv2s = 1.0f / (2.0f * sigma * sigma);

    size_t r0 = (size_t)(i * TT + bh) * PROJD;
    size_t r1 = (size_t)(i * TT + bp) * PROJD;
    size_t r2 = (size_t)(i * TT + bt) * PROJD;
    size_t rh = (size_t)(i * TT + 0) * PROJD;
    size_t rt = (size_t)(i * TT + (TT - 1)) * PROJD;
    float oma = 1.0f - alpha;
    float xs = 0.0f, as = 0.0f, ht = 0.0f;
    #pragma unroll
    for (int h = 0; h < 2; h++) {
        int c = h * 128 + lane * 4;
        float g0[4], g1[4], g2[4], gh[4], gt[4];
        ld_rec4(g_neg_h, g_neg_l, r0 + c, g0);
        ld_rec4(g_neg_h, g_neg_l, r1 + c, g1);
        ld_rec4(g_neg_h, g_neg_l, r2 + c, g2);
        ld_rec4(g_neg_h, g_neg_l, rh + c, gh);
        ld_rec4(g_neg_h, g_neg_l, rt + c, gt);
        #pragma unroll
        for (int e = 0; e < 4; e++) {
            float aa = oma * g0[e] + alpha * g2[e];
            float x  = g1[e] - oma * g0[e] - alpha * g2[e];
            xs += x * x;
            as += aa * aa;
            ht += gh[e] * gt[e];
            __nv_bfloat16 ahv = __float2bfloat16(aa);
            size_t o = (size_t)i * PROJD + c + e;
            g_a_h[o] = ahv;
            g_a_l[o] = __float2bfloat16(aa - __bfloat162float(ahv));
        }
    }
    xs = warp_sum(xs);
    as = warp_sum(as);
    ht = warp_sum(ht);
    if (lane == 0) {
        g_inv2s[i] = inv2s;
        g_asq[i]   = as;
        g_numer[i] = expf(-xs * inv2s);
        float z = 0.3f - ht;
        g_ht[i] = log1pf(expf(z));
        int pos = atomicAdd(&g_bucket_cnt[bp], 1);
        g_bitems[bp * NI + pos] = i;
    }
}

// ============ Kernel 3: build chunk table ============
__global__ void chunk_kernel()
{
    if (threadIdx.x == 0) {
        int n = 0;
        for (int t = 0; t < TT; t++) {
            int c = g_bucket_cnt[t];
            for (int off = 0; off < c; off += 64) {
                g_chunk_t[n] = t;
                g_chunk_off[n] = off;
                n++;
            }
        }
        g_nchunks = n;
    }
}

// ============ Kernel 4: dist GEMM — one 64i x 64j tile per CTA ============
#define DK2   128    // k-chunk
#define DLD2  136    // padded k leading dim
#define DSTG  72
#define D2_AH   0
#define D2_AL   (D2_AH + 64 * DLD2 * 2)      // 17408 each
#define D2_BH   (D2_AL + 64 * DLD2 * 2)      // 34816
#define D2_BL   (D2_BH + 64 * DLD2 * 2)
#define D2_END  (D2_BL + 64 * DLD2 * 2)      // 69632
#define D2_IDX  (D2_END)
#define DIST_SMEM (D2_IDX + 64 * 4 + 16)
// stage overlays the A region (written only after all MMAs of the tile)
#define D2_STG  0

__global__ void __launch_bounds__(256, 2) dist_mma_kernel()
{
    extern __shared__ char smem_raw[];
    __nv_bfloat16* Ah = (__nv_bfloat16*)(smem_raw + D2_AH);
    __nv_bfloat16* Al = (__nv_bfloat16*)(smem_raw + D2_AL);
    __nv_bfloat16* Bh = (__nv_bfloat16*)(smem_raw + D2_BH);
    __nv_bfloat16* Bl = (__nv_bfloat16*)(smem_raw + D2_BL);
    float* stage = (float*)(smem_raw + D2_STG);
    int* sitems = (int*)(smem_raw + D2_IDX);

    int cidx = blockIdx.y;
    if (cidx >= g_nchunks) return;
    int t   = g_chunk_t[cidx];
    int off = g_chunk_off[cidx];
    int cc  = min(64, g_bucket_cnt[t] - off);
    int j0  = blockIdx.x * 64;

    int tid = threadIdx.x;
    int wid = tid >> 5;
    int lane = tid & 31;
    int wm = wid >> 2;    // 0..1 -> i rows wm*32
    int wn = wid & 3;     // 0..3 -> j cols wn*16

    if (tid < 64)
        sitems[tid] = g_bitems[t * NI + off + ((tid < cc) ? tid : 0)];
    __syncthreads();

    wmma::fragment<wmma::accumulator, 16, 16, 16, float> acc[2];
    wmma::fill_fragment(acc[0], 0.0f);
    wmma::fill_fragment(acc[1], 0.0f);

    #pragma unroll
    for (int kc = 0; kc < 2; kc++) {
        if (kc) __syncthreads();    // tiles consumed before reload
        int kbase = kc * DK2;
        // ---- load A chunk: 64 rows x 128 k (gather), hi/lo ----
        #pragma unroll
        for (int it = 0; it < 4; it++) {
            int flat = it * 256 + tid;      // 0..1023
            int r  = flat >> 4;             // 0..63
            int k8 = flat & 15;
            size_t src = (size_t)sitems[r] * PROJD + kbase + k8 * 8;
            *(uint4*)&Ah[r * DLD2 + k8 * 8] = *(const uint4*)&g_a_h[src];
            *(uint4*)&Al[r * DLD2 + k8 * 8] = *(const uint4*)&g_a_l[src];
        }
        // ---- load B chunk: 64 j-rows x 128 k, hi/lo ----
        #pragma unroll
        for (int it = 0; it < 4; it++) {
            int flat = it * 256 + tid;
            int jr = flat >> 4;
            int k8 = flat & 15;
            size_t src = (size_t)((j0 + jr) * TT + t) * PROJD + kbase + k8 * 8;
            *(uint4*)&Bh[jr * DLD2 + k8 * 8] = *(const uint4*)&g_neg_h[src];
            *(uint4*)&Bl[jr * DLD2 + k8 * 8] = *(const uint4*)&g_neg_l[src];
        }
        __syncthreads();

        #pragma unroll
        for (int kt = 0; kt < DK2 / 16; kt++) {
            wmma::fragment<wmma::matrix_a, 16, 16, 16, __nv_bfloat16, wmma::row_major> ah[2], al[2];
            wmma::fragment<wmma::matrix_b, 16, 16, 16, __nv_bfloat16, wmma::col_major> bh, bl;
            #pragma unroll
            for (int mt = 0; mt < 2; mt++) {
                int row0 = wm * 32 + mt * 16;
                wmma::load_matrix_sync(ah[mt], Ah + row0 * DLD2 + kt * 16, DLD2);
                wmma::load_matrix_sync(al[mt], Al + row0 * DLD2 + kt * 16, DLD2);
            }
            wmma::load_matrix_sync(bh, Bh + (wn * 16) * DLD2 + kt * 16, DLD2);
            wmma::load_matrix_sync(bl, Bl + (wn * 16) * DLD2 + kt * 16, DLD2);
            #pragma unroll
            for (int mt = 0; mt < 2; mt++) {
                wmma::mma_sync(acc[mt], ah[mt], bh, acc[mt]);
                wmma::mma_sync(acc[mt], al[mt], bh, acc[mt]);
                wmma::mma_sync(acc[mt], ah[mt], bl, acc[mt]);
            }
        }
    }

    __syncthreads();   // all MMAs done before stage overlays A
    #pragma unroll
    for (int mt = 0; mt < 2; mt++)
        wmma::store_matrix_sync(stage + (wm * 32 + mt * 16) * DSTG + wn * 16,
                                acc[mt], DSTG, wmma::mem_row_major);
    __syncthreads();

    // ---- epilogue: 64x64 outputs, 16 per thread ----
    int r  = tid >> 2;                 // 0..63
    int c0 = (tid & 3) * 16;
    if (r < cc) {
        int i = sitems[r];
        float asqi = g_asq[i];
        float is2  = g_inv2s[i];
        #pragma unroll
        for (int u = 0; u < 16; u++) {
            int j = j0 + c0 + u;
            float cross = stage[r * DSTG + c0 + u];
            float d = -(g_nsq[j * TT + t] - 2.0f * cross + asqi) * is2;
            if (j == i) { g_self[i] = d; d = -10000.0f; }
            g_dist[(size_t)i * NNEG + j] = d;
        }
    }
}

// ============ Kernel 5: warp-per-row top-5 + brownian term ============
__global__ void __launch_bounds__(256) topk_kernel()
{
    int wid  = threadIdx.x >> 5;
    int lane = threadIdx.x & 31;
    int i = blockIdx.x * 8 + wid;
    const float* row = &g_dist[(size_t)i * NNEG];

    float t5[5] = {-1e30f, -1e30f, -1e30f, -1e30f, -1e30f};
    #pragma unroll 4
    for (int k = 0; k < NNEG / 128; k++) {
        float4 v = *(const float4*)&row[k * 128 + lane * 4];
        ins5(t5, v.x); ins5(t5, v.y); ins5(t5, v.z); ins5(t5, v.w);
    }
    #pragma unroll
    for (int off = 16; off > 0; off >>= 1) {
        float b0 = __shfl_xor_sync(0xffffffffu, t5[0], off);
        float b1 = __shfl_xor_sync(0xffffffffu, t5[1], off);
        float b2 = __shfl_xor_sync(0xffffffffu, t5[2], off);
        float b3 = __shfl_xor_sync(0xffffffffu, t5[3], off);
        float b4 = __shfl_xor_sync(0xffffffffu, t5[4], off);
        ins5(t5, b0); ins5(t5, b1); ins5(t5, b2); ins5(t5, b3); ins5(t5, b4);
    }
    if (lane == 0) {
        float deno = expf(g_self[i]);
        #pragma unroll
        for (int k = 0; k < 5; k++) deno += expf(t5[k]);
        g_brown[i] = g_numer[i] / deno;
    }
}

// ============ Kernel 6: deterministic final reduction ============
__global__ void __launch_bounds__(256) final_kernel(float* __restrict__ out)
{
    __shared__ float sb[256], sh[256];
    int tid = threadIdx.x;
    float b = 0.0f, h = 0.0f;
    for (int i = tid; i < NI; i += 256) { b += g_brown[i]; h += g_ht[i]; }
    sb[tid] = b; sh[tid] = h;
    __syncthreads();
    for (int s = 128; s > 0; s >>= 1) {
        if (tid < s) { sb[tid] += sb[tid + s]; sh[tid] += sh[tid + s]; }
        __syncthreads();
    }
    if (tid == 0) {
        out[0] = sb[0] / (float)NI;
        out[1] = sh[0] / (float)NI;
    }
}

// ==================== launch ====================
extern "C" void kernel_launch(void* const* d_in, const int* in_sizes, int n_in,
                              void* d_out, int out_size)
{
    const float* fe     = (const float*)d_in[0];
    const float* ofe    = (const float*)d_in[1];
    const float* W      = (const float*)d_in[2];
    const float* bias   = (const float*)d_in[3];
    const int*   bridge = (const int*)d_in[4];
    float* out = (float*)d_out;

    cudaFuncSetAttribute(proj_mma_kernel, cudaFuncAttributeMaxDynamicSharedMemorySize, PROJ_SMEM);
    cudaFuncSetAttribute(dist_mma_kernel, cudaFuncAttributeMaxDynamicSharedMemorySize, DIST_SMEM);

    convert_w_kernel<<<HIDD, PROJD>>>(W);
    proj_mma_kernel<<<800, 256, PROJ_SMEM>>>(fe, ofe, bias);

    bridge_prep_kernel<<<NI / 8, 256>>>(bridge);
    chunk_kernel<<<1, 32>>>();
    dist_mma_kernel<<<dim3(NNEG / 64, MAXC), 256, DIST_SMEM>>>();
    topk_kernel<<<NI / 8, 256>>>();
    final_kernel<<<1, 256>>>(out);
}

// round 8
// speedup vs baseline: 2.3691x; 1.1064x over previous
#include <cstdint>
#include <stdint.h>
#include <cuda_runtime.h>
#include <cuda_bf16.h>
#include <mma.h>
#include <math.h>

using namespace nvcuda;

#define BSZ   16
#define TT    16
#define QQ    100
#define HIDD  256
#define PROJD 256
#define NI    1600    // BS*Q
#define MROWS 25600   // BS*T*Q
#define NNEG  3200
#define NJB   (NNEG / 64)      // 50 j-blocks
#define MAXC  (NI / 64 + TT)   // 41 chunk slots upper bound

// -------- scratch (device globals; no allocation allowed) --------
__device__ __nv_bfloat16 g_neg_h[NNEG * TT * PROJD];   // 26.2 MB  [j, t, c] hi
__device__ __nv_bfloat16 g_neg_l[NNEG * TT * PROJD];   // 26.2 MB  lo
__device__ float g_nsq[NNEG * TT];                     // sum(neg^2) per (j,t)
__device__ __nv_bfloat16 g_a_h[NI * PROJD];
__device__ __nv_bfloat16 g_a_l[NI * PROJD];
__device__ float g_asq[NI];
__device__ float g_numer[NI];
__device__ float g_inv2s[NI];
__device__ float g_part[NI * 256];               // per-(i, jblock) top-5, 1.6 MB
__device__ float g_self[NI];
__device__ float g_brown[NI];
__device__ float g_ht[NI];
__device__ __nv_bfloat16 g_wt_hi[PROJD * HIDD];  // W^T split-hi  [n][k]
__device__ __nv_bfloat16 g_wt_lo[PROJD * HIDD];  // W^T split-lo  [n][k]
__device__ int g_bucket_cnt[TT];
__device__ int g_bitems[TT * NI];                // bucket item lists

__device__ __forceinline__ float warp_sum(float v) {
    #pragma unroll
    for (int o = 16; o > 0; o >>= 1) v += __shfl_xor_sync(0xffffffffu, v, o);
    return v;
}

// reconstruct 4 floats from hi/lo bf16 arrays at index idx (8-byte aligned)
__device__ __forceinline__ void ld_rec4(const __nv_bfloat16* __restrict__ h,
                                        const __nv_bfloat16* __restrict__ l,
                                        size_t idx, float* out) {
    __nv_bfloat162 h0 = *(const __nv_bfloat162*)&h[idx];
    __nv_bfloat162 h1 = *(const __nv_bfloat162*)&h[idx + 2];
    __nv_bfloat162 l0 = *(const __nv_bfloat162*)&l[idx];
    __nv_bfloat162 l1 = *(const __nv_bfloat162*)&l[idx + 2];
    out[0] = __bfloat162float(h0.x) + __bfloat162float(l0.x);
    out[1] = __bfloat162float(h0.y) + __bfloat162float(l0.y);
    out[2] = __bfloat162float(h1.x) + __bfloat162float(l1.x);
    out[3] = __bfloat162float(h1.y) + __bfloat162float(l1.y);
}

// sorted-desc top-5 insert
__device__ __forceinline__ void ins5(float* t5, float v) {
    if (v > t5[4]) {
        if (v > t5[0])      { t5[4]=t5[3]; t5[3]=t5[2]; t5[2]=t5[1]; t5[1]=t5[0]; t5[0]=v; }
        else if (v > t5[1]) { t5[4]=t5[3]; t5[3]=t5[2]; t5[2]=t5[1]; t5[1]=v; }
        else if (v > t5[2]) { t5[4]=t5[3]; t5[3]=t5[2]; t5[2]=v; }
        else if (v > t5[3]) { t5[4]=t5[3]; t5[3]=v; }
        else                { t5[4]=v; }
    }
}

// ============ Kernel 0: W -> W^T split into bf16 hi/lo (+ zero bucket counters) ============
__global__ void __launch_bounds__(256) convert_w_kernel(const float* __restrict__ W)
{
    if (blockIdx.x == 0 && threadIdx.x < TT) g_bucket_cnt[threadIdx.x] = 0;
    int k = blockIdx.x;      // 0..255 (HID)
    int n = threadIdx.x;     // 0..255 (PROJ)
    float v = W[k * PROJD + n];
    __nv_bfloat16 h = __float2bfloat16(v);
    g_wt_hi[n * HIDD + k] = h;
    g_wt_lo[n * HIDD + k] = __float2bfloat16(v - __bfloat162float(h));
}

// ============ Kernel 1: wmma bf16-split projection (64M x 256N per CTA) ============
#define KC   64
#define LDA  72
#define LDB  72
#define STG_LD 260

#define OFF_BIAS  0
#define OFF_U     1024
#define OFF_A_HI  (OFF_U)
#define OFF_A_LO  (OFF_A_HI + 64 * LDA * 2)
#define OFF_B_HI  (OFF_A_LO + 64 * LDA * 2)
#define OFF_B_LO  (OFF_B_HI + 256 * LDB * 2)
#define TILES_END (OFF_B_LO + 256 * LDB * 2)
#define STG_END   (OFF_U + 64 * STG_LD * 4)
#define PROJ_SMEM (STG_END > TILES_END ? STG_END : TILES_END)

__global__ void __launch_bounds__(256, 2) proj_mma_kernel(
    const float* __restrict__ fe, const float* __restrict__ ofe,
    const float* __restrict__ bias)
{
    extern __shared__ char smem_raw[];
    float* bias_s = (float*)(smem_raw + OFF_BIAS);
    __nv_bfloat16* Ah = (__nv_bfloat16*)(smem_raw + OFF_A_HI);
    __nv_bfloat16* Al = (__nv_bfloat16*)(smem_raw + OFF_A_LO);
    __nv_bfloat16* Bh = (__nv_bfloat16*)(smem_raw + OFF_B_HI);
    __nv_bfloat16* Bl = (__nv_bfloat16*)(smem_raw + OFF_B_LO);
    float* stage = (float*)(smem_raw + OFF_U);

    int tid  = threadIdx.x;
    int wid  = tid >> 5;
    int lane = tid & 31;

    int b = blockIdx.x;
    const float* A = (b < 400) ? fe : ofe;
    int base = (b < 400) ? 0 : NI;
    int m0   = (b % 400) * 64;

    bias_s[tid] = bias[tid];

    int wm = wid >> 2;
    int wn = wid & 3;

    wmma::fragment<wmma::accumulator, 16, 16, 16, float> acc[2][4];
    #pragma unroll
    for (int mt = 0; mt < 2; mt++)
        #pragma unroll
        for (int nt = 0; nt < 4; nt++)
            wmma::fill_fragment(acc[mt][nt], 0.0f);

    for (int c = 0; c < 4; c++) {
        int k0 = c * KC;
        __syncthreads();
        #pragma unroll
        for (int it = 0; it < 4; it++) {
            int flat = it * 256 + tid;
            int row  = flat >> 4;
            int j    = flat & 15;
            float4 v = *(const float4*)&A[(size_t)(m0 + row) * HIDD + k0 + j * 4];
            __nv_bfloat16 h0 = __float2bfloat16(v.x);
            __nv_bfloat16 h1 = __float2bfloat16(v.y);
            __nv_bfloat16 h2 = __float2bfloat16(v.z);
            __nv_bfloat16 h3 = __float2bfloat16(v.w);
            __nv_bfloat16 l0 = __float2bfloat16(v.x - __bfloat162float(h0));
            __nv_bfloat16 l1 = __float2bfloat16(v.y - __bfloat162float(h1));
            __nv_bfloat16 l2 = __float2bfloat16(v.z - __bfloat162float(h2));
            __nv_bfloat16 l3 = __float2bfloat16(v.w - __bfloat162float(h3));
            int o = row * LDA + j * 4;
            *(__nv_bfloat162*)&Ah[o]     = __nv_bfloat162{h0, h1};
            *(__nv_bfloat162*)&Ah[o + 2] = __nv_bfloat162{h2, h3};
            *(__nv_bfloat162*)&Al[o]     = __nv_bfloat162{l0, l1};
            *(__nv_bfloat162*)&Al[o + 2] = __nv_bfloat162{l2, l3};
        }
        #pragma unroll
        for (int it = 0; it < 8; it++) {
            int flat = it * 256 + tid;
            int n = flat >> 3;
            int u = flat & 7;
            uint4 vh = *(const uint4*)&g_wt_hi[(size_t)n * HIDD + k0 + u * 8];
            uint4 vl = *(const uint4*)&g_wt_lo[(size_t)n * HIDD + k0 + u * 8];
            *(uint4*)&Bh[n * LDB + u * 8] = vh;
            *(uint4*)&Bl[n * LDB + u * 8] = vl;
        }
        __syncthreads();

        #pragma unroll
        for (int kt = 0; kt < KC / 16; kt++) {
            wmma::fragment<wmma::matrix_a, 16, 16, 16, __nv_bfloat16, wmma::row_major> ah[2], al[2];
            #pragma unroll
            for (int mt = 0; mt < 2; mt++) {
                int row0 = wm * 32 + mt * 16;
                wmma::load_matrix_sync(ah[mt], Ah + row0 * LDA + kt * 16, LDA);
                wmma::load_matrix_sync(al[mt], Al + row0 * LDA + kt * 16, LDA);
            }
            #pragma unroll
            for (int nt = 0; nt < 4; nt++) {
                int n0 = wn * 64 + nt * 16;
                wmma::fragment<wmma::matrix_b, 16, 16, 16, __nv_bfloat16, wmma::col_major> bh, bl;
                wmma::load_matrix_sync(bh, Bh + n0 * LDB + kt * 16, LDB);
                wmma::load_matrix_sync(bl, Bl + n0 * LDB + kt * 16, LDB);
                #pragma unroll
                for (int mt = 0; mt < 2; mt++) {
                    wmma::mma_sync(acc[mt][nt], ah[mt], bh, acc[mt][nt]);
                    wmma::mma_sync(acc[mt][nt], al[mt], bh, acc[mt][nt]);
                    wmma::mma_sync(acc[mt][nt], ah[mt], bl, acc[mt][nt]);
                }
            }
        }
    }

    __syncthreads();
    #pragma unroll
    for (int mt = 0; mt < 2; mt++) {
        int row0 = wm * 32 + mt * 16;
        #pragma unroll
        for (int nt = 0; nt < 4; nt++) {
            int n0 = wn * 64 + nt * 16;
            wmma::store_matrix_sync(stage + row0 * STG_LD + n0, acc[mt][nt],
                                    STG_LD, wmma::mem_row_major);
        }
    }
    __syncthreads();

    for (int rr = 0; rr < 8; rr++) {
        int r = wid * 8 + rr;
        float v[8];
        float ss = 0.0f;
        #pragma unroll
        for (int u = 0; u < 8; u++) {
            int cidx = lane + 32 * u;
            float x = stage[r * STG_LD + cidx] + bias_s[cidx];
            v[u] = x;
            ss += x * x;
        }
        ss = warp_sum(ss);
        float inv = rsqrtf(ss);
        int m = m0 + r;
        int q = m % QQ;
        int t = (m / QQ) % TT;
        int bs = m / (QQ * TT);
        int orow = (base + bs * QQ + q) * TT + t;
        #pragma unroll
        for (int u = 0; u < 8; u++) {
            float x = v[u] * inv;
            __nv_bfloat16 h = __float2bfloat16(x);
            size_t o = (size_t)orow * PROJD + lane + 32 * u;
            g_neg_h[o] = h;
            g_neg_l[o] = __float2bfloat16(x - __bfloat162float(h));
        }
        if (lane == 0) g_nsq[orow] = ss * inv * inv;
    }
}

// ============ Kernel 2: bridge prep + fused head-tail + bucket push ============
__global__ void __launch_bounds__(256) bridge_prep_kernel(const int* __restrict__ bridge)
{
    int warp = threadIdx.x >> 5;
    int lane = threadIdx.x & 31;
    int i = blockIdx.x * 8 + warp;        // 0..1599
    int bh = bridge[i * 3 + 0];
    int bp = bridge[i * 3 + 1];
    int bt = bridge[i * 3 + 2];
    float bhf = (float)bh, bpf = (float)bp, btf = (float)bt;
    float alpha = (bpf - bhf) / (btf - bhf);
    float sigma = alpha * (btf - bpf);
    float inv2s = 1.0f / (2.0f * sigma * sigma);

    size_t r0 = (size_t)(i * TT + bh) * PROJD;
    size_t r1 = (size_t)(i * TT + bp) * PROJD;
    size_t r2 = (size_t)(i * TT + bt) * PROJD;
    size_t rh = (size_t)(i * TT + 0) * PROJD;
    size_t rt = (size_t)(i * TT + (TT - 1)) * PROJD;
    float oma = 1.0f - alpha;
    float xs = 0.0f, as = 0.0f, ht = 0.0f;
    #pragma unroll
    for (int h = 0; h < 2; h++) {
        int c = h * 128 + lane * 4;
        float g0[4], g1[4], g2[4], gh[4], gt[4];
        ld_rec4(g_neg_h, g_neg_l, r0 + c, g0);
        ld_rec4(g_neg_h, g_neg_l, r1 + c, g1);
        ld_rec4(g_neg_h, g_neg_l, r2 + c, g2);
        ld_rec4(g_neg_h, g_neg_l, rh + c, gh);
        ld_rec4(g_neg_h, g_neg_l, rt + c, gt);
        #pragma unroll
        for (int e = 0; e < 4; e++) {
            float aa = oma * g0[e] + alpha * g2[e];
            float x  = g1[e] - oma * g0[e] - alpha * g2[e];
            xs += x * x;
            as += aa * aa;
            ht += gh[e] * gt[e];
            __nv_bfloat16 ahv = __float2bfloat16(aa);
            size_t o = (size_t)i * PROJD + c + e;
            g_a_h[o] = ahv;
            g_a_l[o] = __float2bfloat16(aa - __bfloat162float(ahv));
        }
    }
    xs = warp_sum(xs);
    as = warp_sum(as);
    ht = warp_sum(ht);
    if (lane == 0) {
        g_inv2s[i] = inv2s;
        g_asq[i]   = as;
        g_numer[i] = expf(-xs * inv2s);
        float z = 0.3f - ht;
        g_ht[i] = log1pf(expf(z));
        int pos = atomicAdd(&g_bucket_cnt[bp], 1);
        g_bitems[bp * NI + pos] = i;
    }
}

// ============ Kernel 3: dist GEMM — one 64i x 64j tile per CTA, fused block top-5 ============
#define DK2   128    // k-chunk
#define DLD2  136    // padded k leading dim
#define DSTG  72
#define D2_AH   0
#define D2_AL   (D2_AH + 64 * DLD2 * 2)
#define D2_BH   (D2_AL + 64 * DLD2 * 2)
#define D2_BL   (D2_BH + 64 * DLD2 * 2)
#define D2_END  (D2_BL + 64 * DLD2 * 2)
#define D2_IDX  (D2_END)
#define DIST_SMEM (D2_IDX + 64 * 4 + 16)
#define D2_STG  0    // stage overlays A region

__global__ void __launch_bounds__(256, 2) dist_mma_kernel()
{
    extern __shared__ char smem_raw[];
    __nv_bfloat16* Ah = (__nv_bfloat16*)(smem_raw + D2_AH);
    __nv_bfloat16* Al = (__nv_bfloat16*)(smem_raw + D2_AL);
    __nv_bfloat16* Bh = (__nv_bfloat16*)(smem_raw + D2_BH);
    __nv_bfloat16* Bl = (__nv_bfloat16*)(smem_raw + D2_BL);
    float* stage = (float*)(smem_raw + D2_STG);
    int* sitems = (int*)(smem_raw + D2_IDX);

    // ---- map blockIdx.y -> (t, off) via prefix over bucket counts ----
    int cidx = blockIdx.y;
    int t = -1, off = 0;
    {
        int acc_c = 0;
        #pragma unroll
        for (int tt2 = 0; tt2 < TT; tt2++) {
            int nch = (g_bucket_cnt[tt2] + 63) >> 6;
            if (t < 0 && cidx < acc_c + nch) { t = tt2; off = (cidx - acc_c) * 64; }
            acc_c += nch;
        }
    }
    if (t < 0) return;
    int cc = min(64, g_bucket_cnt[t] - off);
    int jblock = blockIdx.x;
    int j0 = jblock * 64;

    int tid = threadIdx.x;
    int wid = tid >> 5;
    int wm = wid >> 2;    // 0..1 -> i rows wm*32
    int wn = wid & 3;     // 0..3 -> j cols wn*16

    if (tid < 64)
        sitems[tid] = g_bitems[t * NI + off + ((tid < cc) ? tid : 0)];
    __syncthreads();

    wmma::fragment<wmma::accumulator, 16, 16, 16, float> acc[2];
    wmma::fill_fragment(acc[0], 0.0f);
    wmma::fill_fragment(acc[1], 0.0f);

    #pragma unroll
    for (int kc = 0; kc < 2; kc++) {
        if (kc) __syncthreads();
        int kbase = kc * DK2;
        #pragma unroll
        for (int it = 0; it < 4; it++) {
            int flat = it * 256 + tid;
            int r  = flat >> 4;
            int k8 = flat & 15;
            size_t src = (size_t)sitems[r] * PROJD + kbase + k8 * 8;
            *(uint4*)&Ah[r * DLD2 + k8 * 8] = *(const uint4*)&g_a_h[src];
            *(uint4*)&Al[r * DLD2 + k8 * 8] = *(const uint4*)&g_a_l[src];
        }
        #pragma unroll
        for (int it = 0; it < 4; it++) {
            int flat = it * 256 + tid;
            int jr = flat >> 4;
            int k8 = flat & 15;
            size_t src = (size_t)((j0 + jr) * TT + t) * PROJD + kbase + k8 * 8;
            *(uint4*)&Bh[jr * DLD2 + k8 * 8] = *(const uint4*)&g_neg_h[src];
            *(uint4*)&Bl[jr * DLD2 + k8 * 8] = *(const uint4*)&g_neg_l[src];
        }
        __syncthreads();

        #pragma unroll
        for (int kt = 0; kt < DK2 / 16; kt++) {
            wmma::fragment<wmma::matrix_a, 16, 16, 16, __nv_bfloat16, wmma::row_major> ah[2], al[2];
            wmma::fragment<wmma::matrix_b, 16, 16, 16, __nv_bfloat16, wmma::col_major> bh, bl;
            #pragma unroll
            for (int mt = 0; mt < 2; mt++) {
                int row0 = wm * 32 + mt * 16;
                wmma::load_matrix_sync(ah[mt], Ah + row0 * DLD2 + kt * 16, DLD2);
                wmma::load_matrix_sync(al[mt], Al + row0 * DLD2 + kt * 16, DLD2);
            }
            wmma::load_matrix_sync(bh, Bh + (wn * 16) * DLD2 + kt * 16, DLD2);
            wmma::load_matrix_sync(bl, Bl + (wn * 16) * DLD2 + kt * 16, DLD2);
            #pragma unroll
            for (int mt = 0; mt < 2; mt++) {
                wmma::mma_sync(acc[mt], ah[mt], bh, acc[mt]);
                wmma::mma_sync(acc[mt], al[mt], bh, acc[mt]);
                wmma::mma_sync(acc[mt], ah[mt], bl, acc[mt]);
            }
        }
    }

    __syncthreads();
    #pragma unroll
    for (int mt = 0; mt < 2; mt++)
        wmma::store_matrix_sync(stage + (wm * 32 + mt * 16) * DSTG + wn * 16,
                                acc[mt], DSTG, wmma::mem_row_major);
    __syncthreads();

    // ---- epilogue: per-row block top-5 (4 threads per row), no g_dist ----
    int r  = tid >> 2;                 // 0..63
    int c0 = (tid & 3) * 16;
    int i = sitems[r];
    bool valid = (r < cc);
    float asqi = g_asq[i];
    float is2  = g_inv2s[i];
    float t5[5] = {-1e30f, -1e30f, -1e30f, -1e30f, -1e30f};
    #pragma unroll
    for (int u = 0; u < 16; u++) {
        int j = j0 + c0 + u;
        float cross = stage[r * DSTG + c0 + u];
        float d = -(g_nsq[j * TT + t] - 2.0f * cross + asqi) * is2;
        if (j == i) { if (valid) g_self[i] = d; d = -10000.0f; }
        ins5(t5, d);
    }
    // merge across the 4 lanes of this row (lanes differ in bits 0-1)
    #pragma unroll
    for (int o2 = 1; o2 <= 2; o2 <<= 1) {
        float b0 = __shfl_xor_sync(0xffffffffu, t5[0], o2);
        float b1 = __shfl_xor_sync(0xffffffffu, t5[1], o2);
        float b2 = __shfl_xor_sync(0xffffffffu, t5[2], o2);
        float b3 = __shfl_xor_sync(0xffffffffu, t5[3], o2);
        float b4 = __shfl_xor_sync(0xffffffffu, t5[4], o2);
        ins5(t5, b0); ins5(t5, b1); ins5(t5, b2); ins5(t5, b3); ins5(t5, b4);
    }
    if (valid && (tid & 3) == 0) {
        float* dst = &g_part[(size_t)i * 256 + jblock * 5];
        dst[0] = t5[0]; dst[1] = t5[1]; dst[2] = t5[2]; dst[3] = t5[3]; dst[4] = t5[4];
    }
}

// ============ Kernel 4: warp-per-row merge of partial top-5s ============
__global__ void __launch_bounds__(256) topk_kernel()
{
    int wid  = threadIdx.x >> 5;
    int lane = threadIdx.x & 31;
    int i = blockIdx.x * 8 + wid;
    const float* part = &g_part[(size_t)i * 256];

    float t5[5] = {-1e30f, -1e30f, -1e30f, -1e30f, -1e30f};
    for (int k = lane; k < NJB * 5; k += 32) ins5(t5, part[k]);
    #pragma unroll
    for (int off = 16; off > 0; off >>= 1) {
        float b0 = __shfl_xor_sync(0xffffffffu, t5[0], off);
        float b1 = __shfl_xor_sync(0xffffffffu, t5[1], off);
        float b2 = __shfl_xor_sync(0xffffffffu, t5[2], off);
        float b3 = __shfl_xor_sync(0xffffffffu, t5[3], off);
        float b4 = __shfl_xor_sync(0xffffffffu, t5[4], off);
        ins5(t5, b0); ins5(t5, b1); ins5(t5, b2); ins5(t5, b3); ins5(t5, b4);
    }
    if (lane == 0) {
        float deno = expf(g_self[i]);
        #pragma unroll
        for (int k = 0; k < 5; k++) deno += expf(t5[k]);
        g_brown[i] = g_numer[i] / deno;
    }
}

// ============ Kernel 5: deterministic final reduction ============
__global__ void __launch_bounds__(256) final_kernel(float* __restrict__ out)
{
    __shared__ float sb[256], sh[256];
    int tid = threadIdx.x;
    float b = 0.0f, h = 0.0f;
    for (int i = tid; i < NI; i += 256) { b += g_brown[i]; h += g_ht[i]; }
    sb[tid] = b; sh[tid] = h;
    __syncthreads();
    for (int s = 128; s > 0; s >>= 1) {
        if (tid < s) { sb[tid] += sb[tid + s]; sh[tid] += sh[tid + s]; }
        __syncthreads();
    }
    if (tid == 0) {
        out[0] = sb[0] / (float)NI;
        out[1] = sh[0] / (float)NI;
    }
}

// ==================== launch ====================
extern "C" void kernel_launch(void* const* d_in, const int* in_sizes, int n_in,
                              void* d_out, int out_size)
{
    const float* fe     = (const float*)d_in[0];
    const float* ofe    = (const float*)d_in[1];
    const float* W      = (const float*)d_in[2];
    const float* bias   = (const float*)d_in[3];
    const int*   bridge = (const int*)d_in[4];
    float* out = (float*)d_out;

    cudaFuncSetAttribute(proj_mma_kernel, cudaFuncAttributeMaxDynamicSharedMemorySize, PROJ_SMEM);
    cudaFuncSetAttribute(dist_mma_kernel, cudaFuncAttributeMaxDynamicSharedMemorySize, DIST_SMEM);

    convert_w_kernel<<<HIDD, PROJD>>>(W);
    proj_mma_kernel<<<800, 256, PROJ_SMEM>>>(fe, ofe, bias);

    bridge_prep_kernel<<<NI / 8, 256>>>(bridge);
    dist_mma_kernel<<<dim3(NJB, MAXC), 256, DIST_SMEM>>>();
    topk_kernel<<<NI / 8, 256>>>();
    final_kernel<<<1, 256>>>(out);
}

// round 9
// speedup vs baseline: 2.4116x; 1.0179x over previous
#include <cstdint>
#include <stdint.h>
#include <cuda_runtime.h>
#include <cuda_bf16.h>
#include <mma.h>
#include <math.h>

using namespace nvcuda;

#define BSZ   16
#define TT    16
#define QQ    100
#define HIDD  256
#define PROJD 256
#define NI    1600    // BS*Q
#define MROWS 25600   // BS*T*Q
#define NNEG  3200
#define NJB2  (NNEG / 128)     // 25 j-blocks of 128
#define MAXC  (NI / 64 + TT)   // 41 chunk slots upper bound

// -------- scratch (device globals; no allocation allowed) --------
__device__ __nv_bfloat16 g_neg_h[NNEG * TT * PROJD];   // 26.2 MB  [j, t, c] hi
__device__ __nv_bfloat16 g_neg_l[NNEG * TT * PROJD];   // 26.2 MB  lo
__device__ float g_nsq[NNEG * TT];                     // sum(neg^2) per (j,t)
__device__ __nv_bfloat16 g_a_h[NI * PROJD];
__device__ __nv_bfloat16 g_a_l[NI * PROJD];
__device__ float g_asq[NI];
__device__ float g_numer[NI];
__device__ float g_inv2s[NI];
__device__ float g_part[NI * 256];               // per-(i, jblock) top-5
__device__ float g_self[NI];
__device__ float g_brown[NI];
__device__ float g_ht[NI];
__device__ __nv_bfloat16 g_wt_hi[PROJD * HIDD];  // W^T split-hi  [n][k]
__device__ __nv_bfloat16 g_wt_lo[PROJD * HIDD];  // W^T split-lo  [n][k]
__device__ int g_bucket_cnt[TT];
__device__ int g_bitems[TT * NI];                // bucket item lists

__device__ __forceinline__ float warp_sum(float v) {
    #pragma unroll
    for (int o = 16; o > 0; o >>= 1) v += __shfl_xor_sync(0xffffffffu, v, o);
    return v;
}

__device__ __forceinline__ void ld_rec4(const __nv_bfloat16* __restrict__ h,
                                        const __nv_bfloat16* __restrict__ l,
                                        size_t idx, float* out) {
    __nv_bfloat162 h0 = *(const __nv_bfloat162*)&h[idx];
    __nv_bfloat162 h1 = *(const __nv_bfloat162*)&h[idx + 2];
    __nv_bfloat162 l0 = *(const __nv_bfloat162*)&l[idx];
    __nv_bfloat162 l1 = *(const __nv_bfloat162*)&l[idx + 2];
    out[0] = __bfloat162float(h0.x) + __bfloat162float(l0.x);
    out[1] = __bfloat162float(h0.y) + __bfloat162float(l0.y);
    out[2] = __bfloat162float(h1.x) + __bfloat162float(l1.x);
    out[3] = __bfloat162float(h1.y) + __bfloat162float(l1.y);
}

// sorted-desc top-5 insert
__device__ __forceinline__ void ins5(float* t5, float v) {
    if (v > t5[4]) {
        if (v > t5[0])      { t5[4]=t5[3]; t5[3]=t5[2]; t5[2]=t5[1]; t5[1]=t5[0]; t5[0]=v; }
        else if (v > t5[1]) { t5[4]=t5[3]; t5[3]=t5[2]; t5[2]=t5[1]; t5[1]=v; }
        else if (v > t5[2]) { t5[4]=t5[3]; t5[3]=t5[2]; t5[2]=v; }
        else if (v > t5[3]) { t5[4]=t5[3]; t5[3]=v; }
        else                { t5[4]=v; }
    }
}

// ============ Kernel 0: W -> W^T split into bf16 hi/lo (+ zero bucket counters) ============
__global__ void __launch_bounds__(256) convert_w_kernel(const float* __restrict__ W)
{
    if (blockIdx.x == 0 && threadIdx.x < TT) g_bucket_cnt[threadIdx.x] = 0;
    int k = blockIdx.x;
    int n = threadIdx.x;
    float v = W[k * PROJD + n];
    __nv_bfloat16 h = __float2bfloat16(v);
    g_wt_hi[n * HIDD + k] = h;
    g_wt_lo[n * HIDD + k] = __float2bfloat16(v - __bfloat162float(h));
}

// ============ Kernel 1: wmma bf16-split projection (64M x 256N per CTA) ============
#define KC   64
#define LDA  72
#define LDB  72
#define STG_LD 260

#define OFF_BIAS  0
#define OFF_U     1024
#define OFF_A_HI  (OFF_U)
#define OFF_A_LO  (OFF_A_HI + 64 * LDA * 2)
#define OFF_B_HI  (OFF_A_LO + 64 * LDA * 2)
#define OFF_B_LO  (OFF_B_HI + 256 * LDB * 2)
#define TILES_END (OFF_B_LO + 256 * LDB * 2)
#define STG_END   (OFF_U + 64 * STG_LD * 4)
#define PROJ_SMEM (STG_END > TILES_END ? STG_END : TILES_END)

__global__ void __launch_bounds__(256, 2) proj_mma_kernel(
    const float* __restrict__ fe, const float* __restrict__ ofe,
    const float* __restrict__ bias)
{
    extern __shared__ char smem_raw[];
    float* bias_s = (float*)(smem_raw + OFF_BIAS);
    __nv_bfloat16* Ah = (__nv_bfloat16*)(smem_raw + OFF_A_HI);
    __nv_bfloat16* Al = (__nv_bfloat16*)(smem_raw + OFF_A_LO);
    __nv_bfloat16* Bh = (__nv_bfloat16*)(smem_raw + OFF_B_HI);
    __nv_bfloat16* Bl = (__nv_bfloat16*)(smem_raw + OFF_B_LO);
    float* stage = (float*)(smem_raw + OFF_U);

    int tid  = threadIdx.x;
    int wid  = tid >> 5;
    int lane = tid & 31;

    int b = blockIdx.x;
    const float* A = (b < 400) ? fe : ofe;
    int base = (b < 400) ? 0 : NI;
    int m0   = (b % 400) * 64;

    bias_s[tid] = bias[tid];

    int wm = wid >> 2;
    int wn = wid & 3;

    wmma::fragment<wmma::accumulator, 16, 16, 16, float> acc[2][4];
    #pragma unroll
    for (int mt = 0; mt < 2; mt++)
        #pragma unroll
        for (int nt = 0; nt < 4; nt++)
            wmma::fill_fragment(acc[mt][nt], 0.0f);

    for (int c = 0; c < 4; c++) {
        int k0 = c * KC;
        __syncthreads();
        #pragma unroll
        for (int it = 0; it < 4; it++) {
            int flat = it * 256 + tid;
            int row  = flat >> 4;
            int j    = flat & 15;
            float4 v = *(const float4*)&A[(size_t)(m0 + row) * HIDD + k0 + j * 4];
            __nv_bfloat16 h0 = __float2bfloat16(v.x);
            __nv_bfloat16 h1 = __float2bfloat16(v.y);
            __nv_bfloat16 h2 = __float2bfloat16(v.z);
            __nv_bfloat16 h3 = __float2bfloat16(v.w);
            __nv_bfloat16 l0 = __float2bfloat16(v.x - __bfloat162float(h0));
            __nv_bfloat16 l1 = __float2bfloat16(v.y - __bfloat162float(h1));
            __nv_bfloat16 l2 = __float2bfloat16(v.z - __bfloat162float(h2));
            __nv_bfloat16 l3 = __float2bfloat16(v.w - __bfloat162float(h3));
            int o = row * LDA + j * 4;
            *(__nv_bfloat162*)&Ah[o]     = __nv_bfloat162{h0, h1};
            *(__nv_bfloat162*)&Ah[o + 2] = __nv_bfloat162{h2, h3};
            *(__nv_bfloat162*)&Al[o]     = __nv_bfloat162{l0, l1};
            *(__nv_bfloat162*)&Al[o + 2] = __nv_bfloat162{l2, l3};
        }
        #pragma unroll
        for (int it = 0; it < 8; it++) {
            int flat = it * 256 + tid;
            int n = flat >> 3;
            int u = flat & 7;
            uint4 vh = *(const uint4*)&g_wt_hi[(size_t)n * HIDD + k0 + u * 8];
            uint4 vl = *(const uint4*)&g_wt_lo[(size_t)n * HIDD + k0 + u * 8];
            *(uint4*)&Bh[n * LDB + u * 8] = vh;
            *(uint4*)&Bl[n * LDB + u * 8] = vl;
        }
        __syncthreads();

        #pragma unroll
        for (int kt = 0; kt < KC / 16; kt++) {
            wmma::fragment<wmma::matrix_a, 16, 16, 16, __nv_bfloat16, wmma::row_major> ah[2], al[2];
            #pragma unroll
            for (int mt = 0; mt < 2; mt++) {
                int row0 = wm * 32 + mt * 16;
                wmma::load_matrix_sync(ah[mt], Ah + row0 * LDA + kt * 16, LDA);
                wmma::load_matrix_sync(al[mt], Al + row0 * LDA + kt * 16, LDA);
            }
            #pragma unroll
            for (int nt = 0; nt < 4; nt++) {
                int n0 = wn * 64 + nt * 16;
                wmma::fragment<wmma::matrix_b, 16, 16, 16, __nv_bfloat16, wmma::col_major> bh, bl;
                wmma::load_matrix_sync(bh, Bh + n0 * LDB + kt * 16, LDB);
                wmma::load_matrix_sync(bl, Bl + n0 * LDB + kt * 16, LDB);
                #pragma unroll
                for (int mt = 0; mt < 2; mt++) {
                    wmma::mma_sync(acc[mt][nt], ah[mt], bh, acc[mt][nt]);
                    wmma::mma_sync(acc[mt][nt], al[mt], bh, acc[mt][nt]);
                    wmma::mma_sync(acc[mt][nt], ah[mt], bl, acc[mt][nt]);
                }
            }
        }
    }

    __syncthreads();
    #pragma unroll
    for (int mt = 0; mt < 2; mt++) {
        int row0 = wm * 32 + mt * 16;
        #pragma unroll
        for (int nt = 0; nt < 4; nt++) {
            int n0 = wn * 64 + nt * 16;
            wmma::store_matrix_sync(stage + row0 * STG_LD + n0, acc[mt][nt],
                                    STG_LD, wmma::mem_row_major);
        }
    }
    __syncthreads();

    for (int rr = 0; rr < 8; rr++) {
        int r = wid * 8 + rr;
        float v[8];
        float ss = 0.0f;
        #pragma unroll
        for (int u = 0; u < 8; u++) {
            int cidx = lane + 32 * u;
            float x = stage[r * STG_LD + cidx] + bias_s[cidx];
            v[u] = x;
            ss += x * x;
        }
        ss = warp_sum(ss);
        float inv = rsqrtf(ss);
        int m = m0 + r;
        int q = m % QQ;
        int t = (m / QQ) % TT;
        int bs = m / (QQ * TT);
        int orow = (base + bs * QQ + q) * TT + t;
        #pragma unroll
        for (int u = 0; u < 8; u++) {
            float x = v[u] * inv;
            __nv_bfloat16 h = __float2bfloat16(x);
            size_t o = (size_t)orow * PROJD + lane + 32 * u;
            g_neg_h[o] = h;
            g_neg_l[o] = __float2bfloat16(x - __bfloat162float(h));
        }
        if (lane == 0) g_nsq[orow] = ss * inv * inv;
    }
}

// ============ Kernel 2: bridge prep + fused head-tail + bucket push ============
__global__ void __launch_bounds__(256) bridge_prep_kernel(const int* __restrict__ bridge)
{
    int warp = threadIdx.x >> 5;
    int lane = threadIdx.x & 31;
    int i = blockIdx.x * 8 + warp;
    int bh = bridge[i * 3 + 0];
    int bp = bridge[i * 3 + 1];
    int bt = bridge[i * 3 + 2];
    float bhf = (float)bh, bpf = (float)bp, btf = (float)bt;
    float alpha = (bpf - bhf) / (btf - bhf);
    float sigma = alpha * (btf - bpf);
    float inv2s = 1.0f / (2.0f * sigma * sigma);

    size_t r0 = (size_t)(i * TT + bh) * PROJD;
    size_t r1 = (size_t)(i * TT + bp) * PROJD;
    size_t r2 = (size_t)(i * TT + bt) * PROJD;
    size_t rh = (size_t)(i * TT + 0) * PROJD;
    size_t rt = (size_t)(i * TT + (TT - 1)) * PROJD;
    float oma = 1.0f - alpha;
    float xs = 0.0f, as = 0.0f, ht = 0.0f;
    #pragma unroll
    for (int h = 0; h < 2; h++) {
        int c = h * 128 + lane * 4;
        float g0[4], g1[4], g2[4], gh[4], gt[4];
        ld_rec4(g_neg_h, g_neg_l, r0 + c, g0);
        ld_rec4(g_neg_h, g_neg_l, r1 + c, g1);
        ld_rec4(g_neg_h, g_neg_l, r2 + c, g2);
        ld_rec4(g_neg_h, g_neg_l, rh + c, gh);
        ld_rec4(g_neg_h, g_neg_l, rt + c, gt);
        #pragma unroll
        for (int e = 0; e < 4; e++) {
            float aa = oma * g0[e] + alpha * g2[e];
            float x  = g1[e] - oma * g0[e] - alpha * g2[e];
            xs += x * x;
            as += aa * aa;
            ht += gh[e] * gt[e];
            __nv_bfloat16 ahv = __float2bfloat16(aa);
            size_t o = (size_t)i * PROJD + c + e;
            g_a_h[o] = ahv;
            g_a_l[o] = __float2bfloat16(aa - __bfloat162float(ahv));
        }
    }
    xs = warp_sum(xs);
    as = warp_sum(as);
    ht = warp_sum(ht);
    if (lane == 0) {
        g_inv2s[i] = inv2s;
        g_asq[i]   = as;
        g_numer[i] = expf(-xs * inv2s);
        float z = 0.3f - ht;
        g_ht[i] = log1pf(expf(z));
        int pos = atomicAdd(&g_bucket_cnt[bp], 1);
        g_bitems[bp * NI + pos] = i;
    }
}

// ============ Kernel 3: dist GEMM — 64i x 128j per CTA, warp tile 32x32 ============
#define DK2   128    // k-chunk
#define DLD2  136    // padded k leading dim
#define DSTG2 136    // stage leading dim (floats)
#define D3_AH   0
#define D3_AL   (D3_AH + 64 * DLD2 * 2)        // 17408
#define D3_BH   (D3_AL + 64 * DLD2 * 2)        // 34816
#define D3_BL   (D3_BH + 128 * DLD2 * 2)       // +34816
#define D3_END  (D3_BL + 128 * DLD2 * 2)       // 104448
#define D3_IDX  (D3_END)
#define DIST_SMEM (D3_IDX + 64 * 4 + 16)
#define D3_STG  0    // stage (64 x 136 floats = 34816 B) overlays Ah+Al exactly

__global__ void __launch_bounds__(256, 2) dist_mma_kernel()
{
    extern __shared__ char smem_raw[];
    __nv_bfloat16* Ah = (__nv_bfloat16*)(smem_raw + D3_AH);
    __nv_bfloat16* Al = (__nv_bfloat16*)(smem_raw + D3_AL);
    __nv_bfloat16* Bh = (__nv_bfloat16*)(smem_raw + D3_BH);
    __nv_bfloat16* Bl = (__nv_bfloat16*)(smem_raw + D3_BL);
    float* stage = (float*)(smem_raw + D3_STG);
    int* sitems = (int*)(smem_raw + D3_IDX);

    // ---- map blockIdx.y -> (t, off) via prefix over bucket counts ----
    int cidx = blockIdx.y;
    int t = -1, off = 0;
    {
        int acc_c = 0;
        #pragma unroll
        for (int tt2 = 0; tt2 < TT; tt2++) {
            int nch = (g_bucket_cnt[tt2] + 63) >> 6;
            if (t < 0 && cidx < acc_c + nch) { t = tt2; off = (cidx - acc_c) * 64; }
            acc_c += nch;
        }
    }
    if (t < 0) return;
    int cc = min(64, g_bucket_cnt[t] - off);
    int jblock = blockIdx.x;           // 0..24
    int j0 = jblock * 128;

    int tid = threadIdx.x;
    int wid = tid >> 5;
    int wm = wid >> 2;    // 0..1 -> i rows wm*32
    int wn = wid & 3;     // 0..3 -> j cols wn*32

    if (tid < 64)
        sitems[tid] = g_bitems[t * NI + off + ((tid < cc) ? tid : 0)];
    __syncthreads();

    wmma::fragment<wmma::accumulator, 16, 16, 16, float> acc[2][2];
    #pragma unroll
    for (int mt = 0; mt < 2; mt++)
        #pragma unroll
        for (int nt = 0; nt < 2; nt++)
            wmma::fill_fragment(acc[mt][nt], 0.0f);

    #pragma unroll
    for (int kc = 0; kc < 2; kc++) {
        if (kc) __syncthreads();
        int kbase = kc * DK2;
        // ---- load A chunk: 64 rows x 128 k (gather), hi/lo ----
        #pragma unroll
        for (int it = 0; it < 4; it++) {
            int flat = it * 256 + tid;      // 0..1023
            int r  = flat >> 4;             // 0..63
            int k8 = flat & 15;
            size_t src = (size_t)sitems[r] * PROJD + kbase + k8 * 8;
            *(uint4*)&Ah[r * DLD2 + k8 * 8] = *(const uint4*)&g_a_h[src];
            *(uint4*)&Al[r * DLD2 + k8 * 8] = *(const uint4*)&g_a_l[src];
        }
        // ---- load B chunk: 128 j-rows x 128 k, hi/lo ----
        #pragma unroll
        for (int it = 0; it < 8; it++) {
            int flat = it * 256 + tid;      // 0..2047
            int jr = flat >> 4;             // 0..127
            int k8 = flat & 15;
            size_t src = (size_t)((j0 + jr) * TT + t) * PROJD + kbase + k8 * 8;
            *(uint4*)&Bh[jr * DLD2 + k8 * 8] = *(const uint4*)&g_neg_h[src];
            *(uint4*)&Bl[jr * DLD2 + k8 * 8] = *(const uint4*)&g_neg_l[src];
        }
        __syncthreads();

        #pragma unroll
        for (int kt = 0; kt < DK2 / 16; kt++) {
            wmma::fragment<wmma::matrix_a, 16, 16, 16, __nv_bfloat16, wmma::row_major> ah[2], al[2];
            #pragma unroll
            for (int mt = 0; mt < 2; mt++) {
                int row0 = wm * 32 + mt * 16;
                wmma::load_matrix_sync(ah[mt], Ah + row0 * DLD2 + kt * 16, DLD2);
                wmma::load_matrix_sync(al[mt], Al + row0 * DLD2 + kt * 16, DLD2);
            }
            #pragma unroll
            for (int nt = 0; nt < 2; nt++) {
                int n0 = wn * 32 + nt * 16;
                wmma::fragment<wmma::matrix_b, 16, 16, 16, __nv_bfloat16, wmma::col_major> bh, bl;
                wmma::load_matrix_sync(bh, Bh + n0 * DLD2 + kt * 16, DLD2);
                wmma::load_matrix_sync(bl, Bl + n0 * DLD2 + kt * 16, DLD2);
                #pragma unroll
                for (int mt = 0; mt < 2; mt++) {
                    wmma::mma_sync(acc[mt][nt], ah[mt], bh, acc[mt][nt]);
                    wmma::mma_sync(acc[mt][nt], al[mt], bh, acc[mt][nt]);
                    wmma::mma_sync(acc[mt][nt], ah[mt], bl, acc[mt][nt]);
                }
            }
        }
    }

    __syncthreads();   // all MMAs done before stage overlays A
    #pragma unroll
    for (int mt = 0; mt < 2; mt++)
        #pragma unroll
        for (int nt = 0; nt < 2; nt++)
            wmma::store_matrix_sync(stage + (wm * 32 + mt * 16) * DSTG2 + wn * 32 + nt * 16,
                                    acc[mt][nt], DSTG2, wmma::mem_row_major);
    __syncthreads();

    // ---- epilogue: per-row block top-5 (4 threads per row, 32 j each) ----
    int r  = tid >> 2;                 // 0..63
    int c0 = (tid & 3) * 32;
    int i = sitems[r];
    bool valid = (r < cc);
    float asqi = g_asq[i];
    float is2  = g_inv2s[i];
    float t5[5] = {-1e30f, -1e30f, -1e30f, -1e30f, -1e30f};
    #pragma unroll
    for (int u = 0; u < 32; u++) {
        int j = j0 + c0 + u;
        float cross = stage[r * DSTG2 + c0 + u];
        float d = -(g_nsq[j * TT + t] - 2.0f * cross + asqi) * is2;
        if (j == i) { if (valid) g_self[i] = d; d = -10000.0f; }
        ins5(t5, d);
    }
    #pragma unroll
    for (int o2 = 1; o2 <= 2; o2 <<= 1) {
        float b0 = __shfl_xor_sync(0xffffffffu, t5[0], o2);
        float b1 = __shfl_xor_sync(0xffffffffu, t5[1], o2);
        float b2 = __shfl_xor_sync(0xffffffffu, t5[2], o2);
        float b3 = __shfl_xor_sync(0xffffffffu, t5[3], o2);
        float b4 = __shfl_xor_sync(0xffffffffu, t5[4], o2);
        ins5(t5, b0); ins5(t5, b1); ins5(t5, b2); ins5(t5, b3); ins5(t5, b4);
    }
    if (valid && (tid & 3) == 0) {
        float* dst = &g_part[(size_t)i * 256 + jblock * 5];
        dst[0] = t5[0]; dst[1] = t5[1]; dst[2] = t5[2]; dst[3] = t5[3]; dst[4] = t5[4];
    }
}

// ============ Kernel 4: warp-per-row merge of partial top-5s ============
__global__ void __launch_bounds__(256) topk_kernel()
{
    int wid  = threadIdx.x >> 5;
    int lane = threadIdx.x & 31;
    int i = blockIdx.x * 8 + wid;
    const float* part = &g_part[(size_t)i * 256];

    float t5[5] = {-1e30f, -1e30f, -1e30f, -1e30f, -1e30f};
    for (int k = lane; k < NJB2 * 5; k += 32) ins5(t5, part[k]);
    #pragma unroll
    for (int off = 16; off > 0; off >>= 1) {
        float b0 = __shfl_xor_sync(0xffffffffu, t5[0], off);
        float b1 = __shfl_xor_sync(0xffffffffu, t5[1], off);
        float b2 = __shfl_xor_sync(0xffffffffu, t5[2], off);
        float b3 = __shfl_xor_sync(0xffffffffu, t5[3], off);
        float b4 = __shfl_xor_sync(0xffffffffu, t5[4], off);
        ins5(t5, b0); ins5(t5, b1); ins5(t5, b2); ins5(t5, b3); ins5(t5, b4);
    }
    if (lane == 0) {
        float deno = expf(g_self[i]);
        #pragma unroll
        for (int k = 0; k < 5; k++) deno += expf(t5[k]);
        g_brown[i] = g_numer[i] / deno;
    }
}

// ============ Kernel 5: deterministic final reduction ============
__global__ void __launch_bounds__(256) final_kernel(float* __restrict__ out)
{
    __shared__ float sb[256], sh[256];
    int tid = threadIdx.x;
    float b = 0.0f, h = 0.0f;
    for (int i = tid; i < NI; i += 256) { b += g_brown[i]; h += g_ht[i]; }
    sb[tid] = b; sh[tid] = h;
    __syncthreads();
    for (int s = 128; s > 0; s >>= 1) {
        if (tid < s) { sb[tid] += sb[tid + s]; sh[tid] += sh[tid + s]; }
        __syncthreads();
    }
    if (tid == 0) {
        out[0] = sb[0] / (float)NI;
        out[1] = sh[0] / (float)NI;
    }
}

// ==================== launch ====================
extern "C" void kernel_launch(void* const* d_in, const int* in_sizes, int n_in,
                              void* d_out, int out_size)
{
    const float* fe     = (const float*)d_in[0];
    const float* ofe    = (const float*)d_in[1];
    const float* W      = (const float*)d_in[2];
    const float* bias   = (const float*)d_in[3];
    const int*   bridge = (const int*)d_in[4];
    float* out = (float*)d_out;

    cudaFuncSetAttribute(proj_mma_kernel, cudaFuncAttributeMaxDynamicSharedMemorySize, PROJ_SMEM);
    cudaFuncSetAttribute(dist_mma_kernel, cudaFuncAttributeMaxDynamicSharedMemorySize, DIST_SMEM);

    convert_w_kernel<<<HIDD, PROJD>>>(W);
    proj_mma_kernel<<<800, 256, PROJ_SMEM>>>(fe, ofe, bias);

    bridge_prep_kernel<<<NI / 8, 256>>>(bridge);
    dist_mma_kernel<<<dim3(NJB2, MAXC), 256, DIST_SMEM>>>();
    topk_kernel<<<NI / 8, 256>>>();
    final_kernel<<<1, 256>>>(out);
}

// round 10
// speedup vs baseline: 2.5476x; 1.0564x over previous
#include <cstdint>
#include <stdint.h>
#include <cuda_runtime.h>
#include <cuda_bf16.h>
#include <mma.h>
#include <math.h>

using namespace nvcuda;

#define BSZ   16
#define TT    16
#define QQ    100
#define HIDD  256
#define PROJD 256
#define NI    1600    // BS*Q
#define MROWS 25600   // BS*T*Q
#define NNEG  3200
#define NJB2  (NNEG / 128)     // 25 j-blocks of 128
#define MAXC  (NI / 64 + TT)   // 41 chunk slots upper bound

// -------- scratch (device globals; no allocation allowed) --------
__device__ __nv_bfloat16 g_neg_h[NNEG * TT * PROJD];
__device__ __nv_bfloat16 g_neg_l[NNEG * TT * PROJD];
__device__ float g_nsq[NNEG * TT];
__device__ __nv_bfloat16 g_a_h[NI * PROJD];
__device__ __nv_bfloat16 g_a_l[NI * PROJD];
__device__ float g_asq[NI];
__device__ float g_numer[NI];
__device__ float g_inv2s[NI];
__device__ float g_part[NI * 256];
__device__ float g_self[NI];
__device__ float g_brown[NI];
__device__ float g_ht[NI];
__device__ __nv_bfloat16 g_wt_hi[PROJD * HIDD];
__device__ __nv_bfloat16 g_wt_lo[PROJD * HIDD];
__device__ int g_bucket_cnt[TT];
__device__ int g_bitems[TT * NI];

__device__ __forceinline__ float warp_sum(float v) {
    #pragma unroll
    for (int o = 16; o > 0; o >>= 1) v += __shfl_xor_sync(0xffffffffu, v, o);
    return v;
}

__device__ __forceinline__ uint32_t smem_u32(const void* p) {
    uint32_t a;
    asm("{ .reg .u64 t; cvta.to.shared.u64 t, %1; cvt.u32.u64 %0, t; }" : "=r"(a) : "l"(p));
    return a;
}
__device__ __forceinline__ void cp16(uint32_t dst, const void* src) {
    asm volatile("cp.async.cg.shared.global [%0], [%1], 16;" :: "r"(dst), "l"(src));
}
#define CP_COMMIT() asm volatile("cp.async.commit_group;" ::: "memory")
#define CP_WAIT0()  asm volatile("cp.async.wait_group 0;" ::: "memory")
#define CP_WAIT1()  asm volatile("cp.async.wait_group 1;" ::: "memory")

__device__ __forceinline__ void ld_rec4(const __nv_bfloat16* __restrict__ h,
                                        const __nv_bfloat16* __restrict__ l,
                                        size_t idx, float* out) {
    __nv_bfloat162 h0 = *(const __nv_bfloat162*)&h[idx];
    __nv_bfloat162 h1 = *(const __nv_bfloat162*)&h[idx + 2];
    __nv_bfloat162 l0 = *(const __nv_bfloat162*)&l[idx];
    __nv_bfloat162 l1 = *(const __nv_bfloat162*)&l[idx + 2];
    out[0] = __bfloat162float(h0.x) + __bfloat162float(l0.x);
    out[1] = __bfloat162float(h0.y) + __bfloat162float(l0.y);
    out[2] = __bfloat162float(h1.x) + __bfloat162float(l1.x);
    out[3] = __bfloat162float(h1.y) + __bfloat162float(l1.y);
}

// sorted-desc top-5 insert
__device__ __forceinline__ void ins5(float* t5, float v) {
    if (v > t5[4]) {
        if (v > t5[0])      { t5[4]=t5[3]; t5[3]=t5[2]; t5[2]=t5[1]; t5[1]=t5[0]; t5[0]=v; }
        else if (v > t5[1]) { t5[4]=t5[3]; t5[3]=t5[2]; t5[2]=t5[1]; t5[1]=v; }
        else if (v > t5[2]) { t5[4]=t5[3]; t5[3]=t5[2]; t5[2]=v; }
        else if (v > t5[3]) { t5[4]=t5[3]; t5[3]=v; }
        else                { t5[4]=v; }
    }
}

// ============ Kernel 0: W -> W^T split into bf16 hi/lo ============
__global__ void __launch_bounds__(256) convert_w_kernel(const float* __restrict__ W)
{
    if (blockIdx.x == 0 && threadIdx.x < TT) g_bucket_cnt[threadIdx.x] = 0;
    int k = blockIdx.x;
    int n = threadIdx.x;
    float v = W[k * PROJD + n];
    __nv_bfloat16 h = __float2bfloat16(v);
    g_wt_hi[n * HIDD + k] = h;
    g_wt_lo[n * HIDD + k] = __float2bfloat16(v - __bfloat162float(h));
}

// ============ Kernel 1: wmma bf16-split projection (64M x 256N per CTA) ============
#define KC   64
#define LDA  72
#define LDB  72
#define STG_LD 260

#define OFF_BIAS  0
#define OFF_U     1024
#define OFF_A_HI  (OFF_U)
#define OFF_A_LO  (OFF_A_HI + 64 * LDA * 2)
#define OFF_B_HI  (OFF_A_LO + 64 * LDA * 2)
#define OFF_B_LO  (OFF_B_HI + 256 * LDB * 2)
#define TILES_END (OFF_B_LO + 256 * LDB * 2)
#define STG_END   (OFF_U + 64 * STG_LD * 4)
#define PROJ_SMEM (STG_END > TILES_END ? STG_END : TILES_END)

__global__ void __launch_bounds__(256, 2) proj_mma_kernel(
    const float* __restrict__ fe, const float* __restrict__ ofe,
    const float* __restrict__ bias)
{
    extern __shared__ char smem_raw[];
    uint32_t sb = smem_u32(smem_raw);
    float* bias_s = (float*)(smem_raw + OFF_BIAS);
    __nv_bfloat16* Ah = (__nv_bfloat16*)(smem_raw + OFF_A_HI);
    __nv_bfloat16* Al = (__nv_bfloat16*)(smem_raw + OFF_A_LO);
    __nv_bfloat16* Bh = (__nv_bfloat16*)(smem_raw + OFF_B_HI);
    __nv_bfloat16* Bl = (__nv_bfloat16*)(smem_raw + OFF_B_LO);
    float* stage = (float*)(smem_raw + OFF_U);

    int tid  = threadIdx.x;
    int wid  = tid >> 5;
    int lane = tid & 31;

    int b = blockIdx.x;
    const float* A = (b < 400) ? fe : ofe;
    int base = (b < 400) ? 0 : NI;
    int m0   = (b % 400) * 64;

    bias_s[tid] = bias[tid];

    int wm = wid >> 2;
    int wn = wid & 3;

    wmma::fragment<wmma::accumulator, 16, 16, 16, float> acc[2][4];
    #pragma unroll
    for (int mt = 0; mt < 2; mt++)
        #pragma unroll
        for (int nt = 0; nt < 4; nt++)
            wmma::fill_fragment(acc[mt][nt], 0.0f);

    for (int c = 0; c < 4; c++) {
        int k0 = c * KC;
        __syncthreads();
        // ---- issue B chunk via cp.async (overlaps A convert below) ----
        #pragma unroll
        for (int it = 0; it < 8; it++) {
            int flat = it * 256 + tid;
            int n = flat >> 3;
            int u = flat & 7;
            cp16(sb + OFF_B_HI + n * (LDB * 2) + u * 16, &g_wt_hi[(size_t)n * HIDD + k0 + u * 8]);
            cp16(sb + OFF_B_LO + n * (LDB * 2) + u * 16, &g_wt_lo[(size_t)n * HIDD + k0 + u * 8]);
        }
        CP_COMMIT();
        // ---- load & split A chunk: 64 rows x 64 fp32 ----
        #pragma unroll
        for (int it = 0; it < 4; it++) {
            int flat = it * 256 + tid;
            int row  = flat >> 4;
            int j    = flat & 15;
            float4 v = *(const float4*)&A[(size_t)(m0 + row) * HIDD + k0 + j * 4];
            __nv_bfloat16 h0 = __float2bfloat16(v.x);
            __nv_bfloat16 h1 = __float2bfloat16(v.y);
            __nv_bfloat16 h2 = __float2bfloat16(v.z);
            __nv_bfloat16 h3 = __float2bfloat16(v.w);
            __nv_bfloat16 l0 = __float2bfloat16(v.x - __bfloat162float(h0));
            __nv_bfloat16 l1 = __float2bfloat16(v.y - __bfloat162float(h1));
            __nv_bfloat16 l2 = __float2bfloat16(v.z - __bfloat162float(h2));
            __nv_bfloat16 l3 = __float2bfloat16(v.w - __bfloat162float(h3));
            int o = row * LDA + j * 4;
            *(__nv_bfloat162*)&Ah[o]     = __nv_bfloat162{h0, h1};
            *(__nv_bfloat162*)&Ah[o + 2] = __nv_bfloat162{h2, h3};
            *(__nv_bfloat162*)&Al[o]     = __nv_bfloat162{l0, l1};
            *(__nv_bfloat162*)&Al[o + 2] = __nv_bfloat162{l2, l3};
        }
        CP_WAIT0();
        __syncthreads();

        #pragma unroll
        for (int kt = 0; kt < KC / 16; kt++) {
            wmma::fragment<wmma::matrix_a, 16, 16, 16, __nv_bfloat16, wmma::row_major> ah[2], al[2];
            #pragma unroll
            for (int mt = 0; mt < 2; mt++) {
                int row0 = wm * 32 + mt * 16;
                wmma::load_matrix_sync(ah[mt], Ah + row0 * LDA + kt * 16, LDA);
                wmma::load_matrix_sync(al[mt], Al + row0 * LDA + kt * 16, LDA);
            }
            #pragma unroll
            for (int nt = 0; nt < 4; nt++) {
                int n0 = wn * 64 + nt * 16;
                wmma::fragment<wmma::matrix_b, 16, 16, 16, __nv_bfloat16, wmma::col_major> bh, bl;
                wmma::load_matrix_sync(bh, Bh + n0 * LDB + kt * 16, LDB);
                wmma::load_matrix_sync(bl, Bl + n0 * LDB + kt * 16, LDB);
                #pragma unroll
                for (int mt = 0; mt < 2; mt++) {
                    wmma::mma_sync(acc[mt][nt], ah[mt], bh, acc[mt][nt]);
                    wmma::mma_sync(acc[mt][nt], al[mt], bh, acc[mt][nt]);
                    wmma::mma_sync(acc[mt][nt], ah[mt], bl, acc[mt][nt]);
                }
            }
        }
    }

    __syncthreads();
    #pragma unroll
    for (int mt = 0; mt < 2; mt++) {
        int row0 = wm * 32 + mt * 16;
        #pragma unroll
        for (int nt = 0; nt < 4; nt++) {
            int n0 = wn * 64 + nt * 16;
            wmma::store_matrix_sync(stage + row0 * STG_LD + n0, acc[mt][nt],
                                    STG_LD, wmma::mem_row_major);
        }
    }
    __syncthreads();

    for (int rr = 0; rr < 8; rr++) {
        int r = wid * 8 + rr;
        float v[8];
        float ss = 0.0f;
        #pragma unroll
        for (int u = 0; u < 8; u++) {
            int cidx = lane + 32 * u;
            float x = stage[r * STG_LD + cidx] + bias_s[cidx];
            v[u] = x;
            ss += x * x;
        }
        ss = warp_sum(ss);
        float inv = rsqrtf(ss);
        int m = m0 + r;
        int q = m % QQ;
        int t = (m / QQ) % TT;
        int bs = m / (QQ * TT);
        int orow = (base + bs * QQ + q) * TT + t;
        #pragma unroll
        for (int u = 0; u < 8; u++) {
            float x = v[u] * inv;
            __nv_bfloat16 h = __float2bfloat16(x);
            size_t o = (size_t)orow * PROJD + lane + 32 * u;
            g_neg_h[o] = h;
            g_neg_l[o] = __float2bfloat16(x - __bfloat162float(h));
        }
        if (lane == 0) g_nsq[orow] = ss * inv * inv;
    }
}

// ============ Kernel 2: bridge prep + fused head-tail + bucket push ============
__global__ void __launch_bounds__(256) bridge_prep_kernel(const int* __restrict__ bridge)
{
    int warp = threadIdx.x >> 5;
    int lane = threadIdx.x & 31;
    int i = blockIdx.x * 8 + warp;
    int bh = bridge[i * 3 + 0];
    int bp = bridge[i * 3 + 1];
    int bt = bridge[i * 3 + 2];
    float bhf = (float)bh, bpf = (float)bp, btf = (float)bt;
    float alpha = (bpf - bhf) / (btf - bhf);
    float sigma = alpha * (btf - bpf);
    float inv2s = 1.0f / (2.0f * sigma * sigma);

    size_t r0 = (size_t)(i * TT + bh) * PROJD;
    size_t r1 = (size_t)(i * TT + bp) * PROJD;
    size_t r2 = (size_t)(i * TT + bt) * PROJD;
    size_t rh = (size_t)(i * TT + 0) * PROJD;
    size_t rt = (size_t)(i * TT + (TT - 1)) * PROJD;
    float oma = 1.0f - alpha;
    float xs = 0.0f, as = 0.0f, ht = 0.0f;
    #pragma unroll
    for (int h = 0; h < 2; h++) {
        int c = h * 128 + lane * 4;
        float g0[4], g1[4], g2[4], gh[4], gt[4];
        ld_rec4(g_neg_h, g_neg_l, r0 + c, g0);
        ld_rec4(g_neg_h, g_neg_l, r1 + c, g1);
        ld_rec4(g_neg_h, g_neg_l, r2 + c, g2);
        ld_rec4(g_neg_h, g_neg_l, rh + c, gh);
        ld_rec4(g_neg_h, g_neg_l, rt + c, gt);
        #pragma unroll
        for (int e = 0; e < 4; e++) {
            float aa = oma * g0[e] + alpha * g2[e];
            float x  = g1[e] - oma * g0[e] - alpha * g2[e];
            xs += x * x;
            as += aa * aa;
            ht += gh[e] * gt[e];
            __nv_bfloat16 ahv = __float2bfloat16(aa);
            size_t o = (size_t)i * PROJD + c + e;
            g_a_h[o] = ahv;
            g_a_l[o] = __float2bfloat16(aa - __bfloat162float(ahv));
        }
    }
    xs = warp_sum(xs);
    as = warp_sum(as);
    ht = warp_sum(ht);
    if (lane == 0) {
        g_inv2s[i] = inv2s;
        g_asq[i]   = as;
        g_numer[i] = expf(-xs * inv2s);
        float z = 0.3f - ht;
        g_ht[i] = log1pf(expf(z));
        int pos = atomicAdd(&g_bucket_cnt[bp], 1);
        g_bitems[bp * NI + pos] = i;
    }
}

// ============ Kernel 3: dist GEMM — 64i x 128j per CTA, cp.async 2-stage pipeline ============
#define DKC   64     // k-chunk
#define DLD3  72     // padded k leading dim (elements) -> 144B rows
#define DSTG2 136
// per-stage layout (bytes): Ah 0, Al 9216, Bh 18432, Bl 36864; stage size 55296
#define DS_AH   0
#define DS_AL   9216
#define DS_BH   18432
#define DS_BL   36864
#define DS_SZ   55296
#define D3_IDX  (2 * DS_SZ)                 // 110592
#define DIST_SMEM (D3_IDX + 64 * 4 + 16)    // ~110.9 KB

__global__ void __launch_bounds__(256, 2) dist_mma_kernel()
{
    extern __shared__ char smem_raw[];
    uint32_t sbase = smem_u32(smem_raw);
    float* stage = (float*)(smem_raw);       // epilogue overlay of stage-0 buffers
    int* sitems = (int*)(smem_raw + D3_IDX);

    // ---- map blockIdx.y -> (t, off) via prefix over bucket counts ----
    int cidx = blockIdx.y;
    int t = -1, off = 0;
    {
        int acc_c = 0;
        #pragma unroll
        for (int tt2 = 0; tt2 < TT; tt2++) {
            int nch = (g_bucket_cnt[tt2] + 63) >> 6;
            if (t < 0 && cidx < acc_c + nch) { t = tt2; off = (cidx - acc_c) * 64; }
            acc_c += nch;
        }
    }
    if (t < 0) return;
    int cc = min(64, g_bucket_cnt[t] - off);
    int jblock = blockIdx.x;           // 0..24
    int j0 = jblock * 128;

    int tid = threadIdx.x;
    int wid = tid >> 5;
    int wm = wid >> 2;    // 0..1 -> i rows wm*32
    int wn = wid & 3;     // 0..3 -> j cols wn*32

    if (tid < 64)
        sitems[tid] = g_bitems[t * NI + off + ((tid < cc) ? tid : 0)];
    __syncthreads();

    // row/col assignment for async loads (constant across chunks)
    int a_r0 = tid >> 3;               // with it in {0,1}: rows tid>>3 and 32+tid>>3
    int a_k  = tid & 7;
    int ai0 = sitems[a_r0];
    int ai1 = sitems[32 + a_r0];

    wmma::fragment<wmma::accumulator, 16, 16, 16, float> acc[2][2];
    #pragma unroll
    for (int mt = 0; mt < 2; mt++)
        #pragma unroll
        for (int nt = 0; nt < 2; nt++)
            wmma::fill_fragment(acc[mt][nt], 0.0f);

    // prefetch lambda: chunk c into stage buffer buf
    auto prefetch = [&](int c, int buf) {
        int kbase = c * DKC;
        uint32_t st = sbase + buf * DS_SZ;
        // A: 64 rows x 64 k, hi+lo (2 x 2 cp16 per thread)
        {
            uint32_t d0 = st + a_r0 * 144 + a_k * 16;
            uint32_t d1 = st + (32 + a_r0) * 144 + a_k * 16;
            size_t s0 = (size_t)ai0 * PROJD + kbase + a_k * 8;
            size_t s1 = (size_t)ai1 * PROJD + kbase + a_k * 8;
            cp16(d0 + DS_AH, &g_a_h[s0]);
            cp16(d1 + DS_AH, &g_a_h[s1]);
            cp16(d0 + DS_AL, &g_a_l[s0]);
            cp16(d1 + DS_AL, &g_a_l[s1]);
        }
        // B: 128 rows x 64 k, hi+lo (4 x 2 cp16 per thread)
        #pragma unroll
        for (int it = 0; it < 4; it++) {
            int flat = it * 256 + tid;          // 0..1023
            int jr = flat >> 3;                 // 0..127
            int k16 = flat & 7;
            uint32_t d = st + jr * 144 + k16 * 16;
            size_t s = (size_t)((j0 + jr) * TT + t) * PROJD + kbase + k16 * 8;
            cp16(d + DS_BH, &g_neg_h[s]);
            cp16(d + DS_BL, &g_neg_l[s]);
        }
    };

    prefetch(0, 0);
    CP_COMMIT();

    #pragma unroll
    for (int c = 0; c < 4; c++) {
        int buf = c & 1;
        if (c < 3) { prefetch(c + 1, (c + 1) & 1); CP_COMMIT(); CP_WAIT1(); }
        else       { CP_WAIT0(); }
        __syncthreads();

        const __nv_bfloat16* Ah = (const __nv_bfloat16*)(smem_raw + buf * DS_SZ + DS_AH);
        const __nv_bfloat16* Al = (const __nv_bfloat16*)(smem_raw + buf * DS_SZ + DS_AL);
        const __nv_bfloat16* Bh = (const __nv_bfloat16*)(smem_raw + buf * DS_SZ + DS_BH);
        const __nv_bfloat16* Bl = (const __nv_bfloat16*)(smem_raw + buf * DS_SZ + DS_BL);

        #pragma unroll
        for (int kt = 0; kt < DKC / 16; kt++) {
            wmma::fragment<wmma::matrix_a, 16, 16, 16, __nv_bfloat16, wmma::row_major> ah[2], al[2];
            #pragma unroll
            for (int mt = 0; mt < 2; mt++) {
                int row0 = wm * 32 + mt * 16;
                wmma::load_matrix_sync(ah[mt], Ah + row0 * DLD3 + kt * 16, DLD3);
                wmma::load_matrix_sync(al[mt], Al + row0 * DLD3 + kt * 16, DLD3);
            }
            #pragma unroll
            for (int nt = 0; nt < 2; nt++) {
                int n0 = wn * 32 + nt * 16;
                wmma::fragment<wmma::matrix_b, 16, 16, 16, __nv_bfloat16, wmma::col_major> bh, bl;
                wmma::load_matrix_sync(bh, Bh + n0 * DLD3 + kt * 16, DLD3);
                wmma::load_matrix_sync(bl, Bl + n0 * DLD3 + kt * 16, DLD3);
                #pragma unroll
                for (int mt = 0; mt < 2; mt++) {
                    wmma::mma_sync(acc[mt][nt], ah[mt], bh, acc[mt][nt]);
                    wmma::mma_sync(acc[mt][nt], al[mt], bh, acc[mt][nt]);
                    wmma::mma_sync(acc[mt][nt], ah[mt], bl, acc[mt][nt]);
                }
            }
        }
        __syncthreads();   // buffer free for next prefetch
    }

    // ---- stage results (overlay stage-0 buffers; all MMAs done) ----
    #pragma unroll
    for (int mt = 0; mt < 2; mt++)
        #pragma unroll
        for (int nt = 0; nt < 2; nt++)
            wmma::store_matrix_sync(stage + (wm * 32 + mt * 16) * DSTG2 + wn * 32 + nt * 16,
                                    acc[mt][nt], DSTG2, wmma::mem_row_major);
    __syncthreads();

    // ---- epilogue: per-row block top-5 (4 threads per row, 32 j each) ----
    int r  = tid >> 2;                 // 0..63
    int c0 = (tid & 3) * 32;
    int i = sitems[r];
    bool valid = (r < cc);
    float asqi = g_asq[i];
    float is2  = g_inv2s[i];
    float t5[5] = {-1e30f, -1e30f, -1e30f, -1e30f, -1e30f};
    #pragma unroll
    for (int u = 0; u < 32; u++) {
        int j = j0 + c0 + u;
        float cross = stage[r * DSTG2 + c0 + u];
        float d = -(g_nsq[j * TT + t] - 2.0f * cross + asqi) * is2;
        if (j == i) { if (valid) g_self[i] = d; d = -10000.0f; }
        ins5(t5, d);
    }
    #pragma unroll
    for (int o2 = 1; o2 <= 2; o2 <<= 1) {
        float b0 = __shfl_xor_sync(0xffffffffu, t5[0], o2);
        float b1 = __shfl_xor_sync(0xffffffffu, t5[1], o2);
        float b2 = __shfl_xor_sync(0xffffffffu, t5[2], o2);
        float b3 = __shfl_xor_sync(0xffffffffu, t5[3], o2);
        float b4 = __shfl_xor_sync(0xffffffffu, t5[4], o2);
        ins5(t5, b0); ins5(t5, b1); ins5(t5, b2); ins5(t5, b3); ins5(t5, b4);
    }
    if (valid && (tid & 3) == 0) {
        float* dst = &g_part[(size_t)i * 256 + jblock * 5];
        dst[0] = t5[0]; dst[1] = t5[1]; dst[2] = t5[2]; dst[3] = t5[3]; dst[4] = t5[4];
    }
}

// ============ Kernel 4: warp-per-row merge of partial top-5s ============
__global__ void __launch_bounds__(256) topk_kernel()
{
    int wid  = threadIdx.x >> 5;
    int lane = threadIdx.x & 31;
    int i = blockIdx.x * 8 + wid;
    const float* part = &g_part[(size_t)i * 256];

    float t5[5] = {-1e30f, -1e30f, -1e30f, -1e30f, -1e30f};
    for (int k = lane; k < NJB2 * 5; k += 32) ins5(t5, part[k]);
    #pragma unroll
    for (int off = 16; off > 0; off >>= 1) {
        float b0 = __shfl_xor_sync(0xffffffffu, t5[0], off);
        float b1 = __shfl_xor_sync(0xffffffffu, t5[1], off);
        float b2 = __shfl_xor_sync(0xffffffffu, t5[2], off);
        float b3 = __shfl_xor_sync(0xffffffffu, t5[3], off);
        float b4 = __shfl_xor_sync(0xffffffffu, t5[4], off);
        ins5(t5, b0); ins5(t5, b1); ins5(t5, b2); ins5(t5, b3); ins5(t5, b4);
    }
    if (lane == 0) {
        float deno = expf(g_self[i]);
        #pragma unroll
        for (int k = 0; k < 5; k++) deno += expf(t5[k]);
        g_brown[i] = g_numer[i] / deno;
    }
}

// ============ Kernel 5: deterministic final reduction ============
__global__ void __launch_bounds__(256) final_kernel(float* __restrict__ out)
{
    __shared__ float sb[256], sh[256];
    int tid = threadIdx.x;
    float b = 0.0f, h = 0.0f;
    for (int i = tid; i < NI; i += 256) { b += g_brown[i]; h += g_ht[i]; }
    sb[tid] = b; sh[tid] = h;
    __syncthreads();
    for (int s = 128; s > 0; s >>= 1) {
        if (tid < s) { sb[tid] += sb[tid + s]; sh[tid] += sh[tid + s]; }
        __syncthreads();
    }
    if (tid == 0) {
        out[0] = sb[0] / (float)NI;
        out[1] = sh[0] / (float)NI;
    }
}

// ==================== launch ====================
extern "C" void kernel_launch(void* const* d_in, const int* in_sizes, int n_in,
                              void* d_out, int out_size)
{
    const float* fe     = (const float*)d_in[0];
    const float* ofe    = (const float*)d_in[1];
    const float* W      = (const float*)d_in[2];
    const float* bias   = (const float*)d_in[3];
    const int*   bridge = (const int*)d_in[4];
    float* out = (float*)d_out;

    cudaFuncSetAttribute(proj_mma_kernel, cudaFuncAttributeMaxDynamicSharedMemorySize, PROJ_SMEM);
    cudaFuncSetAttribute(dist_mma_kernel, cudaFuncAttributeMaxDynamicSharedMemorySize, DIST_SMEM);

    convert_w_kernel<<<HIDD, PROJD>>>(W);
    proj_mma_kernel<<<800, 256, PROJ_SMEM>>>(fe, ofe, bias);

    bridge_prep_kernel<<<NI / 8, 256>>>(bridge);
    dist_mma_kernel<<<dim3(NJB2, MAXC), 256, DIST_SMEM>>>();
    topk_kernel<<<NI / 8, 256>>>();
    final_kernel<<<1, 256>>>(out);
}